// round 13
// baseline (speedup 1.0000x reference)
#include <cuda_runtime.h>
#include <cuda_fp16.h>
#include <mma.h>
#include <math.h>
using namespace nvcuda;

#define BB 8
#define WW 256
#define FF 16
#define DD 128
#define HH 8
#define NL 4
#define INNER 1024
#define NT (BB*WW*FF)          /* 32768 tokens */
#define QKVLD 3072
#define SCALE 0.08838834764831845f   /* 128^-0.5 */
#define RS (FF*QKVLD)          /* 49152: row stride (per w) in qkv */
#define RO (FF*INNER)          /* 16384: row stride (per w) in o   */

/* ---------------- scratch (static __device__, no allocation) ---------------- */
__device__ float  g_h  [NT*DD];
__device__ __half g_qkv[(size_t)NT*QKVLD];
__device__ __half g_o  [(size_t)NT*INNER];
__device__ __half g_wqh[NL*DD*QKVLD];
__device__ __half g_woh[NL*INNER*DD];

/* ---------------- fast exp on the FMA pipe ---------------- */
__device__ __forceinline__ float fexp(float x)
{
    x = fmaxf(x, -80.0f);
    float z  = x * 1.4426950408889634f;
    float zj = z + 12582912.0f;
    int   k  = __float_as_int(zj) - 0x4B400000;
    float f  = z - (zj - 12582912.0f);
    float p  = 1.3333558146e-3f;
    p = p*f + 9.6181291076e-3f;
    p = p*f + 5.5504108665e-2f;
    p = p*f + 2.4022650696e-1f;
    p = p*f + 6.9314718056e-1f;
    p = p*f + 1.0f;
    return __int_as_float(__float_as_int(p) + (k << 23));
}

__device__ __forceinline__ void cp16(void* smem_dst, const void* gmem_src)
{
    unsigned d = (unsigned)__cvta_generic_to_shared(smem_dst);
    asm volatile("cp.async.cg.shared.global [%0], [%1], 16;\n" :: "r"(d), "l"(gmem_src));
}

/* ---------------- weight conversion fp32 -> fp16 (once per launch) ---------------- */
#define NQW (NL*DD*QKVLD)
#define NOW (NL*INNER*DD)
__global__ void cvtw_kernel(const float* __restrict__ wq, const float* __restrict__ wo)
{
    int i = blockIdx.x*256 + threadIdx.x;
    if (i < NQW) g_wqh[i] = __float2half(wq[i]);
    if (i < NOW) g_woh[i] = __float2half(wo[i]);
}

/* ---------------- embed: convs + value proj + positional encoding ---------------- */
__global__ void embed_kernel(const float* __restrict__ x,
    const float* __restrict__ w1, const float* __restrict__ b1,
    const float* __restrict__ w2, const float* __restrict__ b2,
    const float* __restrict__ w3, const float* __restrict__ b3,
    const float* __restrict__ wv, const float* __restrict__ bv)
{
    int tok = blockIdx.x;
    int d   = threadIdx.x;
    int f   = tok % FF;
    int bw  = tok / FF;
    int w   = bw % WW;
    const float* xp = x + (size_t)(bw - w)*FF + f;

    float s0 = xp[(size_t)w*FF];
    float c1 = b1[f];
    #pragma unroll
    for (int j = 0; j < 4; j++) { int wi = w - (3-j);    if (wi >= 0) c1 += xp[(size_t)wi*FF]*w1[f*4+j]; }
    float c2 = b2[f];
    #pragma unroll
    for (int j = 0; j < 8; j++) { int wi = w - (7-j)*2;  if (wi >= 0) c2 += xp[(size_t)wi*FF]*w2[f*8+j]; }
    float c3 = b3[f];
    #pragma unroll
    for (int j = 0; j < 16; j++){ int wi = w - (15-j)*3; if (wi >= 0) c3 += xp[(size_t)wi*FF]*w3[f*16+j]; }

    float e = s0*wv[d] + c1*wv[DD+d] + c2*wv[2*DD+d] + c3*wv[3*DD+d] + bv[d];

    int   i2  = (d >> 1) * 2;
    float div = expf(-logf(10000.0f)/(float)DD * (float)i2);
    float ang = (float)w * div;
    float pe  = (d & 1) ? cosf(ang) : sinf(ang);

    g_h[(size_t)tok*DD + d] = e + pe;
}

/* ---------------- fused LN + QKV GEMM, 3-stage B ring (1 sync per tile) ---------------- */
#define QAHLD 136
#define QBHLD 136
#define QB_ST (32*QBHLD)
#define QCSLD 72
#define NCHUNK 12
#define QOFF_B (128*QAHLD*2)           /* 34816 */
#define QOFF_C (QOFF_B + 3*QB_ST*2)    /* 60928 */
#define QKV_SMEM (QOFF_C + 128*QCSLD*4) /* 97792 B */

__global__ void __launch_bounds__(256)
qkvln_kernel(const float* __restrict__ h, const __half* __restrict__ Bw,
             __half* __restrict__ C,
             const float* __restrict__ gam, const float* __restrict__ bet)
{
    extern __shared__ char smp[];
    __half* Ah = (__half*)smp;
    float*  Cs = (float*)(smp + QOFF_C);

    int m0 = blockIdx.y * 128;
    int nbase = blockIdx.x * (NCHUNK*128);
    int tid = threadIdx.x, w = tid >> 5;
    int wm = w & 3, wn = w >> 2;

    if (tid < 128) Cs[tid] = gam[tid];
    else           Cs[tid] = bet[tid-128];
    __syncthreads();

    {
        int r = tid >> 1, c0 = (tid & 1)*64;
        const float* hr = h + (size_t)(m0+r)*DD + c0;
        float s = 0.f, ss = 0.f;
        #pragma unroll
        for (int i=0;i<16;i++){
            float4 v = *(const float4*)&hr[i*4];
            s  += v.x+v.y+v.z+v.w;
            ss += v.x*v.x+v.y*v.y+v.z*v.z+v.w*v.w;
        }
        s  += __shfl_xor_sync(~0u, s, 1);
        ss += __shfl_xor_sync(~0u, ss, 1);
        float mean = s * (1.0f/DD);
        float rstd = rsqrtf(ss*(1.0f/DD) - mean*mean + 1e-5f);
        #pragma unroll
        for (int i=0;i<16;i++){
            float4 v = *(const float4*)&hr[i*4];
            int c = c0 + i*4;
            __half2 a = __float22half2_rn(make_float2(
                (v.x-mean)*rstd*Cs[c+0] + Cs[128+c+0],
                (v.y-mean)*rstd*Cs[c+1] + Cs[128+c+1]));
            __half2 b = __float22half2_rn(make_float2(
                (v.z-mean)*rstd*Cs[c+2] + Cs[128+c+2],
                (v.w-mean)*rstd*Cs[c+3] + Cs[128+c+3]));
            *(__half2*)&Ah[r*QAHLD + c]     = a;
            *(__half2*)&Ah[r*QAHLD + c + 2] = b;
        }
    }
    __syncthreads();

    auto issueB = [&](int tt){
        __half* Bst = (__half*)(smp + QOFF_B) + (tt % 3)*QB_ST;
        int k0 = (tt & 3) << 5;
        int n0 = nbase + (tt >> 2)*128;
        #pragma unroll
        for (int i=0;i<2;i++){
            int idx = tid + i*256;
            int r = idx >> 4, c8 = (idx & 15)*8;
            cp16(&Bst[r*QBHLD + c8], &Bw[(size_t)(k0+r)*QKVLD + n0 + c8]);
        }
        asm volatile("cp.async.commit_group;\n");
    };

    const int NTT = NCHUNK*4;
    issueB(0);
    issueB(1);
    for (int c = 0; c < NCHUNK; c++){
        wmma::fragment<wmma::accumulator,16,16,16,float> acc[2][4];
        #pragma unroll
        for (int i=0;i<2;i++)
            #pragma unroll
            for (int j=0;j<4;j++) wmma::fill_fragment(acc[i][j], 0.0f);

        for (int kt = 0; kt < 4; kt++){
            int tt = c*4 + kt;
            if (tt < NTT-1) { asm volatile("cp.async.wait_group 1;\n" ::: "memory"); }
            else            { asm volatile("cp.async.wait_group 0;\n" ::: "memory"); }
            __syncthreads();
            if (tt+2 < NTT) issueB(tt+2);
            __half* Bst = (__half*)(smp + QOFF_B) + (tt % 3)*QB_ST;
            #pragma unroll
            for (int ks = 0; ks < 32; ks += 16){
                wmma::fragment<wmma::matrix_a,16,16,16,__half,wmma::row_major> af[2];
                #pragma unroll
                for (int i=0;i<2;i++)
                    wmma::load_matrix_sync(af[i], &Ah[(wm*32 + i*16)*QAHLD + kt*32 + ks], QAHLD);
                #pragma unroll
                for (int j=0;j<4;j++){
                    wmma::fragment<wmma::matrix_b,16,16,16,__half,wmma::row_major> bf;
                    wmma::load_matrix_sync(bf, &Bst[ks*QBHLD + wn*64 + j*16], QBHLD);
                    wmma::mma_sync(acc[0][j], af[0], bf, acc[0][j]);
                    wmma::mma_sync(acc[1][j], af[1], bf, acc[1][j]);
                }
            }
        }

        int n0 = nbase + c*128;
        #pragma unroll
        for (int pass = 0; pass < 2; pass++){
            __syncthreads();
            if (wn == pass){
                #pragma unroll
                for (int i=0;i<2;i++)
                    #pragma unroll
                    for (int j=0;j<4;j++)
                        wmma::store_matrix_sync(&Cs[(wm*32 + i*16)*QCSLD + j*16],
                                                acc[i][j], QCSLD, wmma::mem_row_major);
            }
            __syncthreads();
            #pragma unroll
            for (int i=0;i<4;i++){
                int idx = tid + i*256;
                int r = idx >> 3, c8 = (idx & 7)*8;
                float4 v0 = *(float4*)&Cs[r*QCSLD + c8];
                float4 v1 = *(float4*)&Cs[r*QCSLD + c8 + 4];
                __half2 hh[4];
                hh[0] = __float22half2_rn(make_float2(v0.x, v0.y));
                hh[1] = __float22half2_rn(make_float2(v0.z, v0.w));
                hh[2] = __float22half2_rn(make_float2(v1.x, v1.y));
                hh[3] = __float22half2_rn(make_float2(v1.z, v1.w));
                *(uint4*)&C[(size_t)(m0+r)*QKVLD + n0 + pass*64 + c8] = *(uint4*)hh;
            }
        }
        __syncthreads();
    }
}

/* ---------------- out-proj GEMM v3: 3-stage ring, 1 sync per tile ---------------- */
#define OAHLD 40
#define OBHLD 136
#define OA_ST (64*OAHLD)
#define OB_ST (32*OBHLD)
#define OST_B ((OA_ST + OB_ST)*2)
#define OCSLD 136
#define WOUT_SMEM (3*OST_B)            /* 41472 B */

__global__ void __launch_bounds__(256)
wgemm_out(const __half* __restrict__ A, const __half* __restrict__ B,
          float* __restrict__ C,
          const float* __restrict__ bias, const float* __restrict__ resid)
{
    extern __shared__ char smp[];
    int m0 = blockIdx.x * 64;
    int tid = threadIdx.x, w = tid >> 5;
    int wm = w & 1, wn = w >> 1;

    wmma::fragment<wmma::accumulator,16,16,16,float> acc[2][2];
    #pragma unroll
    for (int i=0;i<2;i++)
        #pragma unroll
        for (int j=0;j<2;j++) wmma::fill_fragment(acc[i][j], 0.0f);

    auto issue = [&](int t){
        char* stg = smp + (t % 3)*OST_B;
        __half* Ast = (__half*)stg;
        __half* Bst = (__half*)stg + OA_ST;
        int k0 = t << 5;
        {
            int r = tid >> 2, c8 = (tid & 3)*8;
            cp16(&Ast[r*OAHLD + c8], &A[(size_t)(m0+r)*INNER + k0 + c8]);
        }
        #pragma unroll
        for (int i=0;i<2;i++){
            int idx = tid + i*256;
            int r = idx >> 4, c8 = (idx & 15)*8;
            cp16(&Bst[r*OBHLD + c8], &B[(size_t)(k0+r)*DD + c8]);
        }
        asm volatile("cp.async.commit_group;\n");
    };

    const int nt = INNER >> 5;
    issue(0);
    issue(1);
    for (int t = 0; t < nt; t++){
        if (t < nt-1) { asm volatile("cp.async.wait_group 1;\n" ::: "memory"); }
        else          { asm volatile("cp.async.wait_group 0;\n" ::: "memory"); }
        __syncthreads();
        if (t+2 < nt) issue(t+2);
        char* stg = smp + (t % 3)*OST_B;
        __half* Ast = (__half*)stg;
        __half* Bst = (__half*)stg + OA_ST;
        #pragma unroll
        for (int ks = 0; ks < 32; ks += 16){
            wmma::fragment<wmma::matrix_a,16,16,16,__half,wmma::row_major> af[2];
            wmma::fragment<wmma::matrix_b,16,16,16,__half,wmma::row_major> bf[2];
            #pragma unroll
            for (int i=0;i<2;i++)
                wmma::load_matrix_sync(af[i], &Ast[(wm*32 + i*16)*OAHLD + ks], OAHLD);
            #pragma unroll
            for (int j=0;j<2;j++)
                wmma::load_matrix_sync(bf[j], &Bst[ks*OBHLD + wn*32 + j*16], OBHLD);
            #pragma unroll
            for (int i=0;i<2;i++)
                #pragma unroll
                for (int j=0;j<2;j++)
                    wmma::mma_sync(acc[i][j], af[i], bf[j], acc[i][j]);
        }
    }
    __syncthreads();

    float* Cs = (float*)smp;
    #pragma unroll
    for (int i=0;i<2;i++)
        #pragma unroll
        for (int j=0;j<2;j++)
            wmma::store_matrix_sync(&Cs[(wm*32 + i*16)*OCSLD + wn*32 + j*16],
                                    acc[i][j], OCSLD, wmma::mem_row_major);
    __syncthreads();

    #pragma unroll
    for (int i=0;i<8;i++){
        int idx = tid + i*256;
        int r = idx >> 5, c4 = (idx & 31)*4;
        float4 v  = *(float4*)&Cs[r*OCSLD + c4];
        float4 bb = *(const float4*)&bias[c4];
        float4 rr = *(const float4*)&resid[(size_t)(m0+r)*DD + c4];
        v.x += bb.x + rr.x; v.y += bb.y + rr.y;
        v.z += bb.z + rr.z; v.w += bb.w + rr.w;
        *(float4*)&C[(size_t)(m0+r)*DD + c4] = v;
    }
}

/* ---------------- variable attention v3: warp-private staging + register softmax ---------------- */
#define VLD2 136
#define VWB  (48*VLD2)
#define VATTN_SMEM (HH*VWB*2)          /* 104448 B */

__global__ void __launch_bounds__(256, 2)
vattn_kernel(const __half* __restrict__ qkv, __half* __restrict__ o)
{
    extern __shared__ __half vs[];
    int bw = blockIdx.x;
    int w  = threadIdx.x >> 5, lane = threadIdx.x & 31;
    int lg = lane >> 2, lq = lane & 3;
    __half* Wb = vs + w*VWB;
    const __half* base = qkv + (size_t)bw*FF*QKVLD + w*DD;
    __half* op = o + (size_t)bw*FF*INNER + w*DD;

    #pragma unroll
    for (int i=0;i<24;i++){
        int idx = lane + i*32;
        int r = idx >> 4, c8 = (idx & 15)*8;
        int f = r & 15, sel = r >> 4;
        cp16(&Wb[r*VLD2 + c8], base + (size_t)f*QKVLD + sel*INNER + c8);
    }
    asm volatile("cp.async.commit_group;\n");
    asm volatile("cp.async.wait_group 0;\n" ::: "memory");
    __syncwarp();

    wmma::fragment<wmma::accumulator,16,16,16,float> sf;
    wmma::fill_fragment(sf, 0.0f);
    #pragma unroll
    for (int ks = 0; ks < DD; ks += 16){
        wmma::fragment<wmma::matrix_a,16,16,16,__half,wmma::row_major> af;
        wmma::fragment<wmma::matrix_b,16,16,16,__half,wmma::col_major> bf;
        wmma::load_matrix_sync(af, Wb + ks, VLD2);
        wmma::load_matrix_sync(bf, Wb + 16*VLD2 + ks, VLD2);
        wmma::mma_sync(sf, af, bf, sf);
    }

    float m2[2], s2[2], rinv[2];
    #pragma unroll
    for (int hh=0; hh<2; hh++){
        int e0 = hh*2;
        float m = fmaxf(fmaxf(sf.x[e0], sf.x[e0+1]), fmaxf(sf.x[e0+4], sf.x[e0+5]));
        m = fmaxf(m, __shfl_xor_sync(~0u, m, 1));
        m = fmaxf(m, __shfl_xor_sync(~0u, m, 2));
        m2[hh] = m;
    }
    #pragma unroll
    for (int hh=0; hh<2; hh++) s2[hh] = 0.f;
    #pragma unroll
    for (int e=0; e<8; e++){
        int hh = (e>>1)&1;
        float p = fexp((sf.x[e] - m2[hh])*SCALE);
        sf.x[e] = p;
        s2[hh] += p;
    }
    #pragma unroll
    for (int hh=0; hh<2; hh++){
        float s = s2[hh];
        s += __shfl_xor_sync(~0u, s, 1);
        s += __shfl_xor_sync(~0u, s, 2);
        rinv[hh] = 1.0f/s;
    }

    __syncwarp();
    #pragma unroll
    for (int e=0; e<8; e+=2){
        int hh = (e>>1)&1;
        int row = lg + 8*hh;
        int col = lq*2 + 8*(e>>2);
        *(__half2*)&Wb[row*VLD2 + col] =
            __float22half2_rn(make_float2(sf.x[e], sf.x[e+1]));
    }
    __syncwarp();

    wmma::fragment<wmma::matrix_a,16,16,16,__half,wmma::row_major> pf;
    wmma::load_matrix_sync(pf, Wb, VLD2);

    #pragma unroll
    for (int n0 = 0; n0 < DD; n0 += 16){
        wmma::fragment<wmma::accumulator,16,16,16,float> of;
        wmma::fill_fragment(of, 0.0f);
        wmma::fragment<wmma::matrix_b,16,16,16,__half,wmma::row_major> vf;
        wmma::load_matrix_sync(vf, Wb + 32*VLD2 + n0, VLD2);
        wmma::mma_sync(of, pf, vf, of);
        #pragma unroll
        for (int e=0; e<8; e+=2){
            int hh = (e>>1)&1;
            int row = lg + 8*hh;
            int col = n0 + lq*2 + 8*(e>>2);
            float inv = rinv[hh];
            *(__half2*)&op[(size_t)row*INNER + col] =
                __float22half2_rn(make_float2(of.x[e]*inv, of.x[e+1]*inv));
        }
    }
}

/* ---------------- fused temporal attention v3: 512 threads, TI=128 ----------------
   K/V each loaded ONCE per 128-row i-tile (8 iterations x 512 threads = 4096 chunks). */
#define TI    128
#define KHLD  136
#define PHLD  264
#define OFF_PH (256*KHLD*2)                    /* 69632  */
#define OFF_RR (OFF_PH + TI*PHLD*2)            /* 137216 */
#define TATTN_SMEM (OFF_RR + TI*4*4)           /* 139264 */

__global__ void __launch_bounds__(512, 1)
tattn_kernel(const __half* __restrict__ qkv, __half* __restrict__ o)
{
    extern __shared__ char smb[];
    __half* Kh = (__half*)smb;                 /* K, then V */
    __half* Ph = (__half*)(smb + OFF_PH);
    float*  RR = (float*) (smb + OFF_RR);

    int batch = blockIdx.y;
    int hd = batch & 7, f = (batch >> 3) & 15, b = batch >> 7;
    int i0 = blockIdx.x * TI;
    size_t baseQ = ((size_t)(b*WW)*FF + f)*QKVLD + hd*DD;
    size_t baseK = baseQ + INNER;
    size_t baseV = baseQ + 2*INNER;
    size_t baseO = ((size_t)(b*WW)*FF + f)*INNER + hd*DD;
    int tid = threadIdx.x, w = tid >> 5, lane = tid & 31;
    int wm = w & 3, wn = w >> 2;
    int lg = lane >> 2, lq = lane & 3;

    /* async load full K (256 x 128 halves = 4096 16B chunks) */
    #pragma unroll
    for (int i=0;i<8;i++){
        int idx = tid + i*512;
        int r = idx >> 4, c8 = (idx & 15)*8;
        cp16(&Kh[r*KHLD + c8], &qkv[baseK + (size_t)r*RS + c8]);
    }
    asm volatile("cp.async.commit_group;\n");
    asm volatile("cp.async.wait_group 0;\n" ::: "memory");
    __syncthreads();

    /* phase 1: S = Q @ K^T (128 x 256). Q fragments from gmem. */
    const __half* qp = qkv + baseQ + (size_t)i0*RS;
    wmma::fragment<wmma::accumulator,16,16,16,float> sf[2][4];
    #pragma unroll
    for (int i=0;i<2;i++)
        #pragma unroll
        for (int j=0;j<4;j++) wmma::fill_fragment(sf[i][j], 0.0f);
    #pragma unroll
    for (int ks=0; ks<DD; ks+=16){
        wmma::fragment<wmma::matrix_a,16,16,16,__half,wmma::row_major> af[2];
        wmma::fragment<wmma::matrix_b,16,16,16,__half,wmma::col_major> bf[4];
        #pragma unroll
        for (int i=0;i<2;i++)
            wmma::load_matrix_sync(af[i], qp + (size_t)(wm*32 + i*16)*RS + ks, RS);
        #pragma unroll
        for (int j=0;j<4;j++)
            wmma::load_matrix_sync(bf[j], &Kh[(wn*64 + j*16)*KHLD + ks], KHLD);
        #pragma unroll
        for (int i=0;i<2;i++)
            #pragma unroll
            for (int j=0;j<4;j++)
                wmma::mma_sync(sf[i][j], af[i], bf[j], sf[i][j]);
    }
    __syncthreads();                       /* all warps done reading K */

    /* issue V load into Kh (overlaps register softmax) */
    #pragma unroll
    for (int i=0;i<8;i++){
        int idx = tid + i*512;
        int r = idx >> 4, c8 = (idx & 15)*8;
        cp16(&Kh[r*KHLD + c8], &qkv[baseV + (size_t)r*RS + c8]);
    }
    asm volatile("cp.async.commit_group;\n");

    /* register softmax */
    float pm[4];
    #pragma unroll
    for (int i=0;i<2;i++)
        #pragma unroll
        for (int hh=0;hh<2;hh++){
            float m = -1e30f;
            #pragma unroll
            for (int j=0;j<4;j++){
                float* x = sf[i][j].x;
                int e0 = hh*2;
                m = fmaxf(m, fmaxf(fmaxf(x[e0], x[e0+1]), fmaxf(x[e0+4], x[e0+5])));
            }
            pm[i*2+hh] = m;
        }
    #pragma unroll
    for (int u=0;u<4;u++){
        pm[u] = fmaxf(pm[u], __shfl_xor_sync(~0u, pm[u], 1));
        pm[u] = fmaxf(pm[u], __shfl_xor_sync(~0u, pm[u], 2));
    }
    if (lq == 0){
        #pragma unroll
        for (int i=0;i<2;i++)
            #pragma unroll
            for (int hh=0;hh<2;hh++)
                RR[(wm*32 + i*16 + hh*8 + lg)*4 + wn] = pm[i*2+hh];
    }
    __syncthreads();
    float gmax[4];
    #pragma unroll
    for (int i=0;i<2;i++)
        #pragma unroll
        for (int hh=0;hh<2;hh++){
            const float* rr = &RR[(wm*32 + i*16 + hh*8 + lg)*4];
            gmax[i*2+hh] = fmaxf(fmaxf(rr[0], rr[1]), fmaxf(rr[2], rr[3]));
        }
    __syncthreads();

    float ps[4] = {0.f, 0.f, 0.f, 0.f};
    #pragma unroll
    for (int i=0;i<2;i++)
        #pragma unroll
        for (int j=0;j<4;j++){
            float* x = sf[i][j].x;
            #pragma unroll
            for (int e=0;e<8;e++){
                int hh = (e>>1)&1;
                float p = fexp((x[e] - gmax[i*2+hh])*SCALE);
                x[e] = p;
                ps[i*2+hh] += p;
            }
        }
    #pragma unroll
    for (int u=0;u<4;u++){
        ps[u] += __shfl_xor_sync(~0u, ps[u], 1);
        ps[u] += __shfl_xor_sync(~0u, ps[u], 2);
    }
    if (lq == 0){
        #pragma unroll
        for (int i=0;i<2;i++)
            #pragma unroll
            for (int hh=0;hh<2;hh++)
                RR[(wm*32 + i*16 + hh*8 + lg)*4 + wn] = ps[i*2+hh];
    }
    __syncthreads();
    float rinv[4];
    #pragma unroll
    for (int i=0;i<2;i++)
        #pragma unroll
        for (int hh=0;hh<2;hh++){
            const float* rr = &RR[(wm*32 + i*16 + hh*8 + lg)*4];
            rinv[i*2+hh] = 1.0f/(rr[0]+rr[1]+rr[2]+rr[3]);
        }

    /* write unnormalized probs (half) to Ph */
    #pragma unroll
    for (int i=0;i<2;i++)
        #pragma unroll
        for (int j=0;j<4;j++){
            float* x = sf[i][j].x;
            #pragma unroll
            for (int e=0;e<8;e+=2){
                int hh = (e>>1)&1;
                int row = wm*32 + i*16 + hh*8 + lg;
                int col = wn*64 + j*16 + lq*2 + 8*(e>>2);
                *(__half2*)&Ph[row*PHLD + col] =
                    __float22half2_rn(make_float2(x[e], x[e+1]));
            }
        }
    asm volatile("cp.async.wait_group 0;\n" ::: "memory");
    __syncthreads();

    /* phase 2: O = P @ V (128 x 128, K=256). warp tile 32x32. */
    wmma::fragment<wmma::accumulator,16,16,16,float> of[2][2];
    #pragma unroll
    for (int i=0;i<2;i++)
        #pragma unroll
        for (int j=0;j<2;j++) wmma::fill_fragment(of[i][j], 0.0f);
    #pragma unroll
    for (int ks=0; ks<WW; ks+=16){
        wmma::fragment<wmma::matrix_a,16,16,16,__half,wmma::row_major> pf[2];
        wmma::fragment<wmma::matrix_b,16,16,16,__half,wmma::row_major> vf[2];
        #pragma unroll
        for (int i=0;i<2;i++)
            wmma::load_matrix_sync(pf[i], &Ph[(wm*32 + i*16)*PHLD + ks], PHLD);
        #pragma unroll
        for (int j=0;j<2;j++)
            wmma::load_matrix_sync(vf[j], &Kh[ks*KHLD + wn*32 + j*16], KHLD);
        #pragma unroll
        for (int i=0;i<2;i++)
            #pragma unroll
            for (int j=0;j<2;j++)
                wmma::mma_sync(of[i][j], pf[i], vf[j], of[i][j]);
    }

    /* epilogue: o(half) += of * rinv, straight from fragments */
    #pragma unroll
    for (int i=0;i<2;i++)
        #pragma unroll
        for (int j=0;j<2;j++){
            float* x = of[i][j].x;
            #pragma unroll
            for (int e=0;e<8;e+=2){
                int hh = (e>>1)&1;
                int row = wm*32 + i*16 + hh*8 + lg;
                int col = wn*32 + j*16 + lq*2 + 8*(e>>2);
                float inv = rinv[i*2+hh];
                __half2* gp = (__half2*)&o[baseO + (size_t)(i0+row)*RO + col];
                float2 f0 = __half22float2(*gp);
                f0.x += x[e]*inv;
                f0.y += x[e+1]*inv;
                *gp = __float22half2_rn(f0);
            }
        }
}

/* ---------------- head ---------------- */
__global__ void head_kernel(const float* __restrict__ wh, const float* __restrict__ bh,
                            float* __restrict__ out)
{
    int bw = blockIdx.x;
    int n = threadIdx.x >> 5, lane = threadIdx.x & 31;
    const float* hrow = g_h + (size_t)bw*(FF*DD);
    float acc = 0.f;
    #pragma unroll 4
    for (int k = lane; k < FF*DD; k += 32)
        acc += hrow[k]*wh[k*FF + n];
    #pragma unroll
    for (int o=16;o>0;o>>=1) acc += __shfl_xor_sync(~0u, acc, o);
    if (lane == 0) out[bw*FF + n] = acc + bh[n];
}

/* ---------------- launcher ---------------- */
extern "C" void kernel_launch(void* const* d_in, const int* in_sizes, int n_in,
                              void* d_out, int out_size)
{
    (void)in_sizes; (void)n_in; (void)out_size;
    const float* x   = (const float*)d_in[0];
    const float* w1  = (const float*)d_in[1];
    const float* b1  = (const float*)d_in[2];
    const float* w2  = (const float*)d_in[3];
    const float* b2  = (const float*)d_in[4];
    const float* w3  = (const float*)d_in[5];
    const float* b3  = (const float*)d_in[6];
    const float* wv  = (const float*)d_in[7];
    const float* bv  = (const float*)d_in[8];
    const float* lng = (const float*)d_in[9];
    const float* lnb = (const float*)d_in[10];
    const float* wq  = (const float*)d_in[11];
    const float* wo  = (const float*)d_in[12];
    const float* bo  = (const float*)d_in[13];
    const float* wh  = (const float*)d_in[14];
    const float* bh  = (const float*)d_in[15];
    float* out = (float*)d_out;

    float *p_h; __half *p_qkv, *p_o, *p_wqh, *p_woh;
    cudaGetSymbolAddress((void**)&p_h,   g_h);
    cudaGetSymbolAddress((void**)&p_qkv, g_qkv);
    cudaGetSymbolAddress((void**)&p_o,   g_o);
    cudaGetSymbolAddress((void**)&p_wqh, g_wqh);
    cudaGetSymbolAddress((void**)&p_woh, g_woh);

    cudaFuncSetAttribute(tattn_kernel,
        cudaFuncAttributeMaxDynamicSharedMemorySize, TATTN_SMEM);
    cudaFuncSetAttribute(vattn_kernel,
        cudaFuncAttributeMaxDynamicSharedMemorySize, VATTN_SMEM);
    cudaFuncSetAttribute(qkvln_kernel,
        cudaFuncAttributeMaxDynamicSharedMemorySize, QKV_SMEM);
    cudaFuncSetAttribute(wgemm_out,
        cudaFuncAttributeMaxDynamicSharedMemorySize, WOUT_SMEM);

    cvtw_kernel<<<(NQW + 255)/256, 256>>>(wq, wo);
    embed_kernel<<<NT, DD>>>(x, w1, b1, w2, b2, w3, b3, wv, bv);

    for (int l = 0; l < NL; l++) {
        /* fused LN + qkv GEMM : [32768,128]@[128,3072] */
        qkvln_kernel<<<dim3(2, NT/128), 256, QKV_SMEM>>>(
            p_h, p_wqh + (size_t)l*DD*QKVLD, p_qkv, lng + l*DD, lnb + l*DD);

        /* variable attention writes g_o (half) */
        vattn_kernel<<<BB*WW, 256, VATTN_SMEM>>>(p_qkv, p_o);

        /* fused temporal attention accumulates into g_o (half RMW) */
        tattn_kernel<<<dim3(WW/TI, BB*FF*HH), 512, TATTN_SMEM>>>(p_qkv, p_o);

        /* h = o @ Wout[l] + b_out[l] + h : [32768,1024]@[1024,128], fp32 out */
        wgemm_out<<<NT/64, 256, WOUT_SMEM>>>(
            p_o, p_woh + (size_t)l*INNER*DD, p_h, bo + l*DD, p_h);
    }

    head_kernel<<<BB*WW, 512>>>(wh, bh, out);
}

// round 14
// speedup vs baseline: 1.0243x; 1.0243x over previous
#include <cuda_runtime.h>
#include <cuda_fp16.h>
#include <mma.h>
#include <math.h>
using namespace nvcuda;

#define BB 8
#define WW 256
#define FF 16
#define DD 128
#define HH 8
#define NL 4
#define INNER 1024
#define NT (BB*WW*FF)          /* 32768 tokens */
#define QKVLD 3072
#define SCALE 0.08838834764831845f   /* 128^-0.5 */
#define RS (FF*QKVLD)          /* 49152: row stride (per w) in qkv */
#define RO (FF*INNER)          /* 16384: row stride (per w) in o   */

/* ---------------- scratch (static __device__, no allocation) ---------------- */
__device__ float  g_h  [NT*DD];
__device__ __half g_qkv[(size_t)NT*QKVLD];
__device__ __half g_o  [(size_t)NT*INNER];
__device__ __half g_wqh[NL*DD*QKVLD];
__device__ __half g_woh[NL*INNER*DD];

/* ---------------- fast exp on the FMA pipe ---------------- */
__device__ __forceinline__ float fexp(float x)
{
    x = fmaxf(x, -80.0f);
    float z  = x * 1.4426950408889634f;
    float zj = z + 12582912.0f;
    int   k  = __float_as_int(zj) - 0x4B400000;
    float f  = z - (zj - 12582912.0f);
    float p  = 1.3333558146e-3f;
    p = p*f + 9.6181291076e-3f;
    p = p*f + 5.5504108665e-2f;
    p = p*f + 2.4022650696e-1f;
    p = p*f + 6.9314718056e-1f;
    p = p*f + 1.0f;
    return __int_as_float(__float_as_int(p) + (k << 23));
}

__device__ __forceinline__ void cp16(void* smem_dst, const void* gmem_src)
{
    unsigned d = (unsigned)__cvta_generic_to_shared(smem_dst);
    asm volatile("cp.async.cg.shared.global [%0], [%1], 16;\n" :: "r"(d), "l"(gmem_src));
}

/* ---------------- weight conversion fp32 -> fp16 (once per launch) ---------------- */
#define NQW (NL*DD*QKVLD)
#define NOW (NL*INNER*DD)
__global__ void cvtw_kernel(const float* __restrict__ wq, const float* __restrict__ wo)
{
    int i = blockIdx.x*256 + threadIdx.x;
    if (i < NQW) g_wqh[i] = __float2half(wq[i]);
    if (i < NOW) g_woh[i] = __float2half(wo[i]);
}

/* ---------------- embed: convs + value proj + positional encoding ---------------- */
__global__ void embed_kernel(const float* __restrict__ x,
    const float* __restrict__ w1, const float* __restrict__ b1,
    const float* __restrict__ w2, const float* __restrict__ b2,
    const float* __restrict__ w3, const float* __restrict__ b3,
    const float* __restrict__ wv, const float* __restrict__ bv)
{
    int tok = blockIdx.x;
    int d   = threadIdx.x;
    int f   = tok % FF;
    int bw  = tok / FF;
    int w   = bw % WW;
    const float* xp = x + (size_t)(bw - w)*FF + f;

    float s0 = xp[(size_t)w*FF];
    float c1 = b1[f];
    #pragma unroll
    for (int j = 0; j < 4; j++) { int wi = w - (3-j);    if (wi >= 0) c1 += xp[(size_t)wi*FF]*w1[f*4+j]; }
    float c2 = b2[f];
    #pragma unroll
    for (int j = 0; j < 8; j++) { int wi = w - (7-j)*2;  if (wi >= 0) c2 += xp[(size_t)wi*FF]*w2[f*8+j]; }
    float c3 = b3[f];
    #pragma unroll
    for (int j = 0; j < 16; j++){ int wi = w - (15-j)*3; if (wi >= 0) c3 += xp[(size_t)wi*FF]*w3[f*16+j]; }

    float e = s0*wv[d] + c1*wv[DD+d] + c2*wv[2*DD+d] + c3*wv[3*DD+d] + bv[d];

    int   i2  = (d >> 1) * 2;
    float div = expf(-logf(10000.0f)/(float)DD * (float)i2);
    float ang = (float)w * div;
    float pe  = (d & 1) ? cosf(ang) : sinf(ang);

    g_h[(size_t)tok*DD + d] = e + pe;
}

/* ---------------- fused LN + QKV GEMM, 3-stage B ring (1 sync per tile) ---------------- */
#define QAHLD 136
#define QBHLD 136
#define QB_ST (32*QBHLD)
#define QCSLD 72
#define NCHUNK 12
#define QOFF_B (128*QAHLD*2)           /* 34816 */
#define QOFF_C (QOFF_B + 3*QB_ST*2)    /* 60928 */
#define QKV_SMEM (QOFF_C + 128*QCSLD*4) /* 97792 B */

__global__ void __launch_bounds__(256)
qkvln_kernel(const float* __restrict__ h, const __half* __restrict__ Bw,
             __half* __restrict__ C,
             const float* __restrict__ gam, const float* __restrict__ bet)
{
    extern __shared__ char smp[];
    __half* Ah = (__half*)smp;
    float*  Cs = (float*)(smp + QOFF_C);

    int m0 = blockIdx.y * 128;
    int nbase = blockIdx.x * (NCHUNK*128);
    int tid = threadIdx.x, w = tid >> 5;
    int wm = w & 3, wn = w >> 2;

    if (tid < 128) Cs[tid] = gam[tid];
    else           Cs[tid] = bet[tid-128];
    __syncthreads();

    {
        int r = tid >> 1, c0 = (tid & 1)*64;
        const float* hr = h + (size_t)(m0+r)*DD + c0;
        float s = 0.f, ss = 0.f;
        #pragma unroll
        for (int i=0;i<16;i++){
            float4 v = *(const float4*)&hr[i*4];
            s  += v.x+v.y+v.z+v.w;
            ss += v.x*v.x+v.y*v.y+v.z*v.z+v.w*v.w;
        }
        s  += __shfl_xor_sync(~0u, s, 1);
        ss += __shfl_xor_sync(~0u, ss, 1);
        float mean = s * (1.0f/DD);
        float rstd = rsqrtf(ss*(1.0f/DD) - mean*mean + 1e-5f);
        #pragma unroll
        for (int i=0;i<16;i++){
            float4 v = *(const float4*)&hr[i*4];
            int c = c0 + i*4;
            __half2 a = __float22half2_rn(make_float2(
                (v.x-mean)*rstd*Cs[c+0] + Cs[128+c+0],
                (v.y-mean)*rstd*Cs[c+1] + Cs[128+c+1]));
            __half2 b = __float22half2_rn(make_float2(
                (v.z-mean)*rstd*Cs[c+2] + Cs[128+c+2],
                (v.w-mean)*rstd*Cs[c+3] + Cs[128+c+3]));
            *(__half2*)&Ah[r*QAHLD + c]     = a;
            *(__half2*)&Ah[r*QAHLD + c + 2] = b;
        }
    }
    __syncthreads();

    auto issueB = [&](int tt){
        __half* Bst = (__half*)(smp + QOFF_B) + (tt % 3)*QB_ST;
        int k0 = (tt & 3) << 5;
        int n0 = nbase + (tt >> 2)*128;
        #pragma unroll
        for (int i=0;i<2;i++){
            int idx = tid + i*256;
            int r = idx >> 4, c8 = (idx & 15)*8;
            cp16(&Bst[r*QBHLD + c8], &Bw[(size_t)(k0+r)*QKVLD + n0 + c8]);
        }
        asm volatile("cp.async.commit_group;\n");
    };

    const int NTT = NCHUNK*4;
    issueB(0);
    issueB(1);
    for (int c = 0; c < NCHUNK; c++){
        wmma::fragment<wmma::accumulator,16,16,16,float> acc[2][4];
        #pragma unroll
        for (int i=0;i<2;i++)
            #pragma unroll
            for (int j=0;j<4;j++) wmma::fill_fragment(acc[i][j], 0.0f);

        for (int kt = 0; kt < 4; kt++){
            int tt = c*4 + kt;
            if (tt < NTT-1) { asm volatile("cp.async.wait_group 1;\n" ::: "memory"); }
            else            { asm volatile("cp.async.wait_group 0;\n" ::: "memory"); }
            __syncthreads();
            if (tt+2 < NTT) issueB(tt+2);
            __half* Bst = (__half*)(smp + QOFF_B) + (tt % 3)*QB_ST;
            #pragma unroll
            for (int ks = 0; ks < 32; ks += 16){
                wmma::fragment<wmma::matrix_a,16,16,16,__half,wmma::row_major> af[2];
                #pragma unroll
                for (int i=0;i<2;i++)
                    wmma::load_matrix_sync(af[i], &Ah[(wm*32 + i*16)*QAHLD + kt*32 + ks], QAHLD);
                #pragma unroll
                for (int j=0;j<4;j++){
                    wmma::fragment<wmma::matrix_b,16,16,16,__half,wmma::row_major> bf;
                    wmma::load_matrix_sync(bf, &Bst[ks*QBHLD + wn*64 + j*16], QBHLD);
                    wmma::mma_sync(acc[0][j], af[0], bf, acc[0][j]);
                    wmma::mma_sync(acc[1][j], af[1], bf, acc[1][j]);
                }
            }
        }

        int n0 = nbase + c*128;
        #pragma unroll
        for (int pass = 0; pass < 2; pass++){
            __syncthreads();
            if (wn == pass){
                #pragma unroll
                for (int i=0;i<2;i++)
                    #pragma unroll
                    for (int j=0;j<4;j++)
                        wmma::store_matrix_sync(&Cs[(wm*32 + i*16)*QCSLD + j*16],
                                                acc[i][j], QCSLD, wmma::mem_row_major);
            }
            __syncthreads();
            #pragma unroll
            for (int i=0;i<4;i++){
                int idx = tid + i*256;
                int r = idx >> 3, c8 = (idx & 7)*8;
                float4 v0 = *(float4*)&Cs[r*QCSLD + c8];
                float4 v1 = *(float4*)&Cs[r*QCSLD + c8 + 4];
                __half2 hh[4];
                hh[0] = __float22half2_rn(make_float2(v0.x, v0.y));
                hh[1] = __float22half2_rn(make_float2(v0.z, v0.w));
                hh[2] = __float22half2_rn(make_float2(v1.x, v1.y));
                hh[3] = __float22half2_rn(make_float2(v1.z, v1.w));
                *(uint4*)&C[(size_t)(m0+r)*QKVLD + n0 + pass*64 + c8] = *(uint4*)hh;
            }
        }
        __syncthreads();
    }
}

/* ---------------- out-proj GEMM v3: 3-stage ring, 1 sync per tile ---------------- */
#define OAHLD 40
#define OBHLD 136
#define OA_ST (64*OAHLD)
#define OB_ST (32*OBHLD)
#define OST_B ((OA_ST + OB_ST)*2)
#define OCSLD 136
#define WOUT_SMEM (3*OST_B)            /* 41472 B */

__global__ void __launch_bounds__(256)
wgemm_out(const __half* __restrict__ A, const __half* __restrict__ B,
          float* __restrict__ C,
          const float* __restrict__ bias, const float* __restrict__ resid)
{
    extern __shared__ char smp[];
    int m0 = blockIdx.x * 64;
    int tid = threadIdx.x, w = tid >> 5;
    int wm = w & 1, wn = w >> 1;

    wmma::fragment<wmma::accumulator,16,16,16,float> acc[2][2];
    #pragma unroll
    for (int i=0;i<2;i++)
        #pragma unroll
        for (int j=0;j<2;j++) wmma::fill_fragment(acc[i][j], 0.0f);

    auto issue = [&](int t){
        char* stg = smp + (t % 3)*OST_B;
        __half* Ast = (__half*)stg;
        __half* Bst = (__half*)stg + OA_ST;
        int k0 = t << 5;
        {
            int r = tid >> 2, c8 = (tid & 3)*8;
            cp16(&Ast[r*OAHLD + c8], &A[(size_t)(m0+r)*INNER + k0 + c8]);
        }
        #pragma unroll
        for (int i=0;i<2;i++){
            int idx = tid + i*256;
            int r = idx >> 4, c8 = (idx & 15)*8;
            cp16(&Bst[r*OBHLD + c8], &B[(size_t)(k0+r)*DD + c8]);
        }
        asm volatile("cp.async.commit_group;\n");
    };

    const int nt = INNER >> 5;
    issue(0);
    issue(1);
    for (int t = 0; t < nt; t++){
        if (t < nt-1) { asm volatile("cp.async.wait_group 1;\n" ::: "memory"); }
        else          { asm volatile("cp.async.wait_group 0;\n" ::: "memory"); }
        __syncthreads();
        if (t+2 < nt) issue(t+2);
        char* stg = smp + (t % 3)*OST_B;
        __half* Ast = (__half*)stg;
        __half* Bst = (__half*)stg + OA_ST;
        #pragma unroll
        for (int ks = 0; ks < 32; ks += 16){
            wmma::fragment<wmma::matrix_a,16,16,16,__half,wmma::row_major> af[2];
            wmma::fragment<wmma::matrix_b,16,16,16,__half,wmma::row_major> bf[2];
            #pragma unroll
            for (int i=0;i<2;i++)
                wmma::load_matrix_sync(af[i], &Ast[(wm*32 + i*16)*OAHLD + ks], OAHLD);
            #pragma unroll
            for (int j=0;j<2;j++)
                wmma::load_matrix_sync(bf[j], &Bst[ks*OBHLD + wn*32 + j*16], OBHLD);
            #pragma unroll
            for (int i=0;i<2;i++)
                #pragma unroll
                for (int j=0;j<2;j++)
                    wmma::mma_sync(acc[i][j], af[i], bf[j], acc[i][j]);
        }
    }
    __syncthreads();

    float* Cs = (float*)smp;
    #pragma unroll
    for (int i=0;i<2;i++)
        #pragma unroll
        for (int j=0;j<2;j++)
            wmma::store_matrix_sync(&Cs[(wm*32 + i*16)*OCSLD + wn*32 + j*16],
                                    acc[i][j], OCSLD, wmma::mem_row_major);
    __syncthreads();

    #pragma unroll
    for (int i=0;i<8;i++){
        int idx = tid + i*256;
        int r = idx >> 5, c4 = (idx & 31)*4;
        float4 v  = *(float4*)&Cs[r*OCSLD + c4];
        float4 bb = *(const float4*)&bias[c4];
        float4 rr = *(const float4*)&resid[(size_t)(m0+r)*DD + c4];
        v.x += bb.x + rr.x; v.y += bb.y + rr.y;
        v.z += bb.z + rr.z; v.w += bb.w + rr.w;
        *(float4*)&C[(size_t)(m0+r)*DD + c4] = v;
    }
}

/* ---------------- variable attention v3: warp-private staging + register softmax ---------------- */
#define VLD2 136
#define VWB  (48*VLD2)
#define VATTN_SMEM (HH*VWB*2)          /* 104448 B */

__global__ void __launch_bounds__(256, 2)
vattn_kernel(const __half* __restrict__ qkv, __half* __restrict__ o)
{
    extern __shared__ __half vs[];
    int bw = blockIdx.x;
    int w  = threadIdx.x >> 5, lane = threadIdx.x & 31;
    int lg = lane >> 2, lq = lane & 3;
    __half* Wb = vs + w*VWB;
    const __half* base = qkv + (size_t)bw*FF*QKVLD + w*DD;
    __half* op = o + (size_t)bw*FF*INNER + w*DD;

    #pragma unroll
    for (int i=0;i<24;i++){
        int idx = lane + i*32;
        int r = idx >> 4, c8 = (idx & 15)*8;
        int f = r & 15, sel = r >> 4;
        cp16(&Wb[r*VLD2 + c8], base + (size_t)f*QKVLD + sel*INNER + c8);
    }
    asm volatile("cp.async.commit_group;\n");
    asm volatile("cp.async.wait_group 0;\n" ::: "memory");
    __syncwarp();

    wmma::fragment<wmma::accumulator,16,16,16,float> sf;
    wmma::fill_fragment(sf, 0.0f);
    #pragma unroll
    for (int ks = 0; ks < DD; ks += 16){
        wmma::fragment<wmma::matrix_a,16,16,16,__half,wmma::row_major> af;
        wmma::fragment<wmma::matrix_b,16,16,16,__half,wmma::col_major> bf;
        wmma::load_matrix_sync(af, Wb + ks, VLD2);
        wmma::load_matrix_sync(bf, Wb + 16*VLD2 + ks, VLD2);
        wmma::mma_sync(sf, af, bf, sf);
    }

    float m2[2], s2[2], rinv[2];
    #pragma unroll
    for (int hh=0; hh<2; hh++){
        int e0 = hh*2;
        float m = fmaxf(fmaxf(sf.x[e0], sf.x[e0+1]), fmaxf(sf.x[e0+4], sf.x[e0+5]));
        m = fmaxf(m, __shfl_xor_sync(~0u, m, 1));
        m = fmaxf(m, __shfl_xor_sync(~0u, m, 2));
        m2[hh] = m;
    }
    #pragma unroll
    for (int hh=0; hh<2; hh++) s2[hh] = 0.f;
    #pragma unroll
    for (int e=0; e<8; e++){
        int hh = (e>>1)&1;
        float p = fexp((sf.x[e] - m2[hh])*SCALE);
        sf.x[e] = p;
        s2[hh] += p;
    }
    #pragma unroll
    for (int hh=0; hh<2; hh++){
        float s = s2[hh];
        s += __shfl_xor_sync(~0u, s, 1);
        s += __shfl_xor_sync(~0u, s, 2);
        rinv[hh] = 1.0f/s;
    }

    __syncwarp();
    #pragma unroll
    for (int e=0; e<8; e+=2){
        int hh = (e>>1)&1;
        int row = lg + 8*hh;
        int col = lq*2 + 8*(e>>2);
        *(__half2*)&Wb[row*VLD2 + col] =
            __float22half2_rn(make_float2(sf.x[e], sf.x[e+1]));
    }
    __syncwarp();

    wmma::fragment<wmma::matrix_a,16,16,16,__half,wmma::row_major> pf;
    wmma::load_matrix_sync(pf, Wb, VLD2);

    #pragma unroll
    for (int n0 = 0; n0 < DD; n0 += 16){
        wmma::fragment<wmma::accumulator,16,16,16,float> of;
        wmma::fill_fragment(of, 0.0f);
        wmma::fragment<wmma::matrix_b,16,16,16,__half,wmma::row_major> vf;
        wmma::load_matrix_sync(vf, Wb + 32*VLD2 + n0, VLD2);
        wmma::mma_sync(of, pf, vf, of);
        #pragma unroll
        for (int e=0; e<8; e+=2){
            int hh = (e>>1)&1;
            int row = lg + 8*hh;
            int col = n0 + lq*2 + 8*(e>>2);
            float inv = rinv[hh];
            *(__half2*)&op[(size_t)row*INNER + col] =
                __float22half2_rn(make_float2(of.x[e]*inv, of.x[e+1]*inv));
        }
    }
}

/* ---------------- fused temporal attention v2 (R10): TI=64, 256 threads, 2 blocks/SM ---------------- */
#define TI    64
#define KHLD  136
#define PHLD  264
#define OFF_PH (256*KHLD*2)                    /* 69632  */
#define OFF_RR (OFF_PH + TI*PHLD*2)            /* 103424 */
#define TATTN_SMEM (OFF_RR + TI*4*4)           /* 104448 */

__global__ void __launch_bounds__(256, 2)
tattn_kernel(const __half* __restrict__ qkv, __half* __restrict__ o)
{
    extern __shared__ char smb[];
    __half* Kh = (__half*)smb;                 /* K, then V */
    __half* Ph = (__half*)(smb + OFF_PH);
    float*  RR = (float*) (smb + OFF_RR);

    int batch = blockIdx.y;
    int hd = batch & 7, f = (batch >> 3) & 15, b = batch >> 7;
    int i0 = blockIdx.x * TI;
    size_t baseQ = ((size_t)(b*WW)*FF + f)*QKVLD + hd*DD;
    size_t baseK = baseQ + INNER;
    size_t baseV = baseQ + 2*INNER;
    size_t baseO = ((size_t)(b*WW)*FF + f)*INNER + hd*DD;
    int tid = threadIdx.x, w = tid >> 5, lane = tid & 31;
    int wm = w & 1, wn = w >> 1;
    int lg = lane >> 2, lq = lane & 3;

    /* async load full K (256 x 128 halves = 4096 16B chunks) */
    #pragma unroll
    for (int i=0;i<16;i++){
        int idx = tid + i*256;
        int r = idx >> 4, c8 = (idx & 15)*8;
        cp16(&Kh[r*KHLD + c8], &qkv[baseK + (size_t)r*RS + c8]);
    }
    asm volatile("cp.async.commit_group;\n");
    asm volatile("cp.async.wait_group 0;\n" ::: "memory");
    __syncthreads();

    /* phase 1: S = Q @ K^T (64 x 256). Q fragments from gmem. */
    const __half* qp = qkv + baseQ + (size_t)i0*RS;
    wmma::fragment<wmma::accumulator,16,16,16,float> sf[2][4];
    #pragma unroll
    for (int i=0;i<2;i++)
        #pragma unroll
        for (int j=0;j<4;j++) wmma::fill_fragment(sf[i][j], 0.0f);
    #pragma unroll
    for (int ks=0; ks<DD; ks+=16){
        wmma::fragment<wmma::matrix_a,16,16,16,__half,wmma::row_major> af[2];
        wmma::fragment<wmma::matrix_b,16,16,16,__half,wmma::col_major> bf[4];
        #pragma unroll
        for (int i=0;i<2;i++)
            wmma::load_matrix_sync(af[i], qp + (size_t)(wm*32 + i*16)*RS + ks, RS);
        #pragma unroll
        for (int j=0;j<4;j++)
            wmma::load_matrix_sync(bf[j], &Kh[(wn*64 + j*16)*KHLD + ks], KHLD);
        #pragma unroll
        for (int i=0;i<2;i++)
            #pragma unroll
            for (int j=0;j<4;j++)
                wmma::mma_sync(sf[i][j], af[i], bf[j], sf[i][j]);
    }
    __syncthreads();                       /* all warps done reading K */

    /* issue V load into Kh (overlaps register softmax) */
    #pragma unroll
    for (int i=0;i<16;i++){
        int idx = tid + i*256;
        int r = idx >> 4, c8 = (idx & 15)*8;
        cp16(&Kh[r*KHLD + c8], &qkv[baseV + (size_t)r*RS + c8]);
    }
    asm volatile("cp.async.commit_group;\n");

    /* register softmax */
    float pm[4];
    #pragma unroll
    for (int i=0;i<2;i++)
        #pragma unroll
        for (int hh=0;hh<2;hh++){
            float m = -1e30f;
            #pragma unroll
            for (int j=0;j<4;j++){
                float* x = sf[i][j].x;
                int e0 = hh*2;
                m = fmaxf(m, fmaxf(fmaxf(x[e0], x[e0+1]), fmaxf(x[e0+4], x[e0+5])));
            }
            pm[i*2+hh] = m;
        }
    #pragma unroll
    for (int u=0;u<4;u++){
        pm[u] = fmaxf(pm[u], __shfl_xor_sync(~0u, pm[u], 1));
        pm[u] = fmaxf(pm[u], __shfl_xor_sync(~0u, pm[u], 2));
    }
    if (lq == 0){
        #pragma unroll
        for (int i=0;i<2;i++)
            #pragma unroll
            for (int hh=0;hh<2;hh++)
                RR[(wm*32 + i*16 + hh*8 + lg)*4 + wn] = pm[i*2+hh];
    }
    __syncthreads();
    float gmax[4];
    #pragma unroll
    for (int i=0;i<2;i++)
        #pragma unroll
        for (int hh=0;hh<2;hh++){
            const float* rr = &RR[(wm*32 + i*16 + hh*8 + lg)*4];
            gmax[i*2+hh] = fmaxf(fmaxf(rr[0], rr[1]), fmaxf(rr[2], rr[3]));
        }
    __syncthreads();

    float ps[4] = {0.f, 0.f, 0.f, 0.f};
    #pragma unroll
    for (int i=0;i<2;i++)
        #pragma unroll
        for (int j=0;j<4;j++){
            float* x = sf[i][j].x;
            #pragma unroll
            for (int e=0;e<8;e++){
                int hh = (e>>1)&1;
                float p = fexp((x[e] - gmax[i*2+hh])*SCALE);
                x[e] = p;
                ps[i*2+hh] += p;
            }
        }
    #pragma unroll
    for (int u=0;u<4;u++){
        ps[u] += __shfl_xor_sync(~0u, ps[u], 1);
        ps[u] += __shfl_xor_sync(~0u, ps[u], 2);
    }
    if (lq == 0){
        #pragma unroll
        for (int i=0;i<2;i++)
            #pragma unroll
            for (int hh=0;hh<2;hh++)
                RR[(wm*32 + i*16 + hh*8 + lg)*4 + wn] = ps[i*2+hh];
    }
    __syncthreads();
    float rinv[4];
    #pragma unroll
    for (int i=0;i<2;i++)
        #pragma unroll
        for (int hh=0;hh<2;hh++){
            const float* rr = &RR[(wm*32 + i*16 + hh*8 + lg)*4];
            rinv[i*2+hh] = 1.0f/(rr[0]+rr[1]+rr[2]+rr[3]);
        }

    /* write unnormalized probs (half) to Ph */
    #pragma unroll
    for (int i=0;i<2;i++)
        #pragma unroll
        for (int j=0;j<4;j++){
            float* x = sf[i][j].x;
            #pragma unroll
            for (int e=0;e<8;e+=2){
                int hh = (e>>1)&1;
                int row = wm*32 + i*16 + hh*8 + lg;
                int col = wn*64 + j*16 + lq*2 + 8*(e>>2);
                *(__half2*)&Ph[row*PHLD + col] =
                    __float22half2_rn(make_float2(x[e], x[e+1]));
            }
        }
    asm volatile("cp.async.wait_group 0;\n" ::: "memory");
    __syncthreads();

    /* phase 2: O = P @ V (64 x 128, K=256). warp tile 32x32. */
    wmma::fragment<wmma::accumulator,16,16,16,float> of[2][2];
    #pragma unroll
    for (int i=0;i<2;i++)
        #pragma unroll
        for (int j=0;j<2;j++) wmma::fill_fragment(of[i][j], 0.0f);
    #pragma unroll
    for (int ks=0; ks<WW; ks+=16){
        wmma::fragment<wmma::matrix_a,16,16,16,__half,wmma::row_major> pf[2];
        wmma::fragment<wmma::matrix_b,16,16,16,__half,wmma::row_major> vf[2];
        #pragma unroll
        for (int i=0;i<2;i++)
            wmma::load_matrix_sync(pf[i], &Ph[(wm*32 + i*16)*PHLD + ks], PHLD);
        #pragma unroll
        for (int j=0;j<2;j++)
            wmma::load_matrix_sync(vf[j], &Kh[ks*KHLD + wn*32 + j*16], KHLD);
        #pragma unroll
        for (int i=0;i<2;i++)
            #pragma unroll
            for (int j=0;j<2;j++)
                wmma::mma_sync(of[i][j], pf[i], vf[j], of[i][j]);
    }

    /* epilogue: o(half) += of * rinv, straight from fragments */
    #pragma unroll
    for (int i=0;i<2;i++)
        #pragma unroll
        for (int j=0;j<2;j++){
            float* x = of[i][j].x;
            #pragma unroll
            for (int e=0;e<8;e+=2){
                int hh = (e>>1)&1;
                int row = wm*32 + i*16 + hh*8 + lg;
                int col = wn*32 + j*16 + lq*2 + 8*(e>>2);
                float inv = rinv[i*2+hh];
                __half2* gp = (__half2*)&o[baseO + (size_t)(i0+row)*RO + col];
                float2 f0 = __half22float2(*gp);
                f0.x += x[e]*inv;
                f0.y += x[e+1]*inv;
                *gp = __float22half2_rn(f0);
            }
        }
}

/* ---------------- head ---------------- */
__global__ void head_kernel(const float* __restrict__ wh, const float* __restrict__ bh,
                            float* __restrict__ out)
{
    int bw = blockIdx.x;
    int n = threadIdx.x >> 5, lane = threadIdx.x & 31;
    const float* hrow = g_h + (size_t)bw*(FF*DD);
    float acc = 0.f;
    #pragma unroll 4
    for (int k = lane; k < FF*DD; k += 32)
        acc += hrow[k]*wh[k*FF + n];
    #pragma unroll
    for (int o=16;o>0;o>>=1) acc += __shfl_xor_sync(~0u, acc, o);
    if (lane == 0) out[bw*FF + n] = acc + bh[n];
}

/* ---------------- launcher ---------------- */
extern "C" void kernel_launch(void* const* d_in, const int* in_sizes, int n_in,
                              void* d_out, int out_size)
{
    (void)in_sizes; (void)n_in; (void)out_size;
    const float* x   = (const float*)d_in[0];
    const float* w1  = (const float*)d_in[1];
    const float* b1  = (const float*)d_in[2];
    const float* w2  = (const float*)d_in[3];
    const float* b2  = (const float*)d_in[4];
    const float* w3  = (const float*)d_in[5];
    const float* b3  = (const float*)d_in[6];
    const float* wv  = (const float*)d_in[7];
    const float* bv  = (const float*)d_in[8];
    const float* lng = (const float*)d_in[9];
    const float* lnb = (const float*)d_in[10];
    const float* wq  = (const float*)d_in[11];
    const float* wo  = (const float*)d_in[12];
    const float* bo  = (const float*)d_in[13];
    const float* wh  = (const float*)d_in[14];
    const float* bh  = (const float*)d_in[15];
    float* out = (float*)d_out;

    float *p_h; __half *p_qkv, *p_o, *p_wqh, *p_woh;
    cudaGetSymbolAddress((void**)&p_h,   g_h);
    cudaGetSymbolAddress((void**)&p_qkv, g_qkv);
    cudaGetSymbolAddress((void**)&p_o,   g_o);
    cudaGetSymbolAddress((void**)&p_wqh, g_wqh);
    cudaGetSymbolAddress((void**)&p_woh, g_woh);

    cudaFuncSetAttribute(tattn_kernel,
        cudaFuncAttributeMaxDynamicSharedMemorySize, TATTN_SMEM);
    cudaFuncSetAttribute(vattn_kernel,
        cudaFuncAttributeMaxDynamicSharedMemorySize, VATTN_SMEM);
    cudaFuncSetAttribute(qkvln_kernel,
        cudaFuncAttributeMaxDynamicSharedMemorySize, QKV_SMEM);
    cudaFuncSetAttribute(wgemm_out,
        cudaFuncAttributeMaxDynamicSharedMemorySize, WOUT_SMEM);

    cvtw_kernel<<<(NQW + 255)/256, 256>>>(wq, wo);
    embed_kernel<<<NT, DD>>>(x, w1, b1, w2, b2, w3, b3, wv, bv);

    for (int l = 0; l < NL; l++) {
        /* fused LN + qkv GEMM : [32768,128]@[128,3072] */
        qkvln_kernel<<<dim3(2, NT/128), 256, QKV_SMEM>>>(
            p_h, p_wqh + (size_t)l*DD*QKVLD, p_qkv, lng + l*DD, lnb + l*DD);

        /* variable attention writes g_o (half) */
        vattn_kernel<<<BB*WW, 256, VATTN_SMEM>>>(p_qkv, p_o);

        /* fused temporal attention accumulates into g_o (half RMW) */
        tattn_kernel<<<dim3(WW/TI, BB*FF*HH), 256, TATTN_SMEM>>>(p_qkv, p_o);

        /* h = o @ Wout[l] + b_out[l] + h : [32768,1024]@[1024,128], fp32 out */
        wgemm_out<<<NT/64, 256, WOUT_SMEM>>>(
            p_o, p_woh + (size_t)l*INNER*DD, p_h, bo + l*DD, p_h);
    }

    head_kernel<<<BB*WW, 512>>>(wh, bh, out);
}

// round 15
// speedup vs baseline: 1.0635x; 1.0383x over previous
#include <cuda_runtime.h>
#include <cuda_fp16.h>
#include <mma.h>
#include <math.h>
using namespace nvcuda;

#define BB 8
#define WW 256
#define FF 16
#define DD 128
#define HH 8
#define NL 4
#define INNER 1024
#define NT (BB*WW*FF)          /* 32768 tokens */
#define QKVLD 3072
#define SCALE 0.08838834764831845f   /* 128^-0.5 */
#define RS (FF*QKVLD)          /* 49152: row stride (per w) in qkv */
#define RO (FF*INNER)          /* 16384: row stride (per w) in o   */

/* ---------------- scratch (static __device__, no allocation) ---------------- */
__device__ float  g_h  [NT*DD];
__device__ __half g_qkv[(size_t)NT*QKVLD];
__device__ __half g_o  [(size_t)NT*INNER];          /* vattn output   */
__device__ __half g_o2 [(size_t)NT*INNER];          /* tattn output   */
__device__ __half g_wqh[NL*DD*QKVLD];
__device__ __half g_woh[NL*INNER*DD];

/* ---------------- fast exp on the FMA pipe ---------------- */
__device__ __forceinline__ float fexp(float x)
{
    x = fmaxf(x, -80.0f);
    float z  = x * 1.4426950408889634f;
    float zj = z + 12582912.0f;
    int   k  = __float_as_int(zj) - 0x4B400000;
    float f  = z - (zj - 12582912.0f);
    float p  = 1.3333558146e-3f;
    p = p*f + 9.6181291076e-3f;
    p = p*f + 5.5504108665e-2f;
    p = p*f + 2.4022650696e-1f;
    p = p*f + 6.9314718056e-1f;
    p = p*f + 1.0f;
    return __int_as_float(__float_as_int(p) + (k << 23));
}

__device__ __forceinline__ void cp16(void* smem_dst, const void* gmem_src)
{
    unsigned d = (unsigned)__cvta_generic_to_shared(smem_dst);
    asm volatile("cp.async.cg.shared.global [%0], [%1], 16;\n" :: "r"(d), "l"(gmem_src));
}

/* ---------------- weight conversion fp32 -> fp16 (once per launch) ---------------- */
#define NQW (NL*DD*QKVLD)
#define NOW (NL*INNER*DD)
__global__ void cvtw_kernel(const float* __restrict__ wq, const float* __restrict__ wo)
{
    int i = blockIdx.x*256 + threadIdx.x;
    if (i < NQW) g_wqh[i] = __float2half(wq[i]);
    if (i < NOW) g_woh[i] = __float2half(wo[i]);
}

/* ---------------- embed: convs + value proj + positional encoding ---------------- */
__global__ void embed_kernel(const float* __restrict__ x,
    const float* __restrict__ w1, const float* __restrict__ b1,
    const float* __restrict__ w2, const float* __restrict__ b2,
    const float* __restrict__ w3, const float* __restrict__ b3,
    const float* __restrict__ wv, const float* __restrict__ bv)
{
    int tok = blockIdx.x;
    int d   = threadIdx.x;
    int f   = tok % FF;
    int bw  = tok / FF;
    int w   = bw % WW;
    const float* xp = x + (size_t)(bw - w)*FF + f;

    float s0 = xp[(size_t)w*FF];
    float c1 = b1[f];
    #pragma unroll
    for (int j = 0; j < 4; j++) { int wi = w - (3-j);    if (wi >= 0) c1 += xp[(size_t)wi*FF]*w1[f*4+j]; }
    float c2 = b2[f];
    #pragma unroll
    for (int j = 0; j < 8; j++) { int wi = w - (7-j)*2;  if (wi >= 0) c2 += xp[(size_t)wi*FF]*w2[f*8+j]; }
    float c3 = b3[f];
    #pragma unroll
    for (int j = 0; j < 16; j++){ int wi = w - (15-j)*3; if (wi >= 0) c3 += xp[(size_t)wi*FF]*w3[f*16+j]; }

    float e = s0*wv[d] + c1*wv[DD+d] + c2*wv[2*DD+d] + c3*wv[3*DD+d] + bv[d];

    int   i2  = (d >> 1) * 2;
    float div = expf(-logf(10000.0f)/(float)DD * (float)i2);
    float ang = (float)w * div;
    float pe  = (d & 1) ? cosf(ang) : sinf(ang);

    g_h[(size_t)tok*DD + d] = e + pe;
}

/* ---------------- fused LN + QKV GEMM (R10 2-stage version) ---------------- */
#define QAHLD 136
#define QBHLD 136
#define QB_ST (32*QBHLD)
#define QCSLD 72
#define NCHUNK 12
#define QKV_SMEM (128*QAHLD*2 + 2*QB_ST*2 + 128*QCSLD*4)   /* 89088 B */

__global__ void __launch_bounds__(256)
qkvln_kernel(const float* __restrict__ h, const __half* __restrict__ Bw,
             __half* __restrict__ C,
             const float* __restrict__ gam, const float* __restrict__ bet)
{
    extern __shared__ char smp[];
    __half* Ah    = (__half*)smp;
    __half* Bh[2] = { (__half*)(smp + 128*QAHLD*2),
                      (__half*)(smp + 128*QAHLD*2) + QB_ST };
    float*  Cs    = (float*)(smp + 128*QAHLD*2 + 2*QB_ST*2);

    int m0 = blockIdx.y * 128;
    int nbase = blockIdx.x * (NCHUNK*128);
    int tid = threadIdx.x, w = tid >> 5;
    int wm = w & 3, wn = w >> 2;

    if (tid < 128) Cs[tid] = gam[tid];
    else           Cs[tid] = bet[tid-128];
    __syncthreads();

    {
        int r = tid >> 1, c0 = (tid & 1)*64;
        const float* hr = h + (size_t)(m0+r)*DD + c0;
        float s = 0.f, ss = 0.f;
        #pragma unroll
        for (int i=0;i<16;i++){
            float4 v = *(const float4*)&hr[i*4];
            s  += v.x+v.y+v.z+v.w;
            ss += v.x*v.x+v.y*v.y+v.z*v.z+v.w*v.w;
        }
        s  += __shfl_xor_sync(~0u, s, 1);
        ss += __shfl_xor_sync(~0u, ss, 1);
        float mean = s * (1.0f/DD);
        float rstd = rsqrtf(ss*(1.0f/DD) - mean*mean + 1e-5f);
        #pragma unroll
        for (int i=0;i<16;i++){
            float4 v = *(const float4*)&hr[i*4];
            int c = c0 + i*4;
            __half2 a = __float22half2_rn(make_float2(
                (v.x-mean)*rstd*Cs[c+0] + Cs[128+c+0],
                (v.y-mean)*rstd*Cs[c+1] + Cs[128+c+1]));
            __half2 b = __float22half2_rn(make_float2(
                (v.z-mean)*rstd*Cs[c+2] + Cs[128+c+2],
                (v.w-mean)*rstd*Cs[c+3] + Cs[128+c+3]));
            *(__half2*)&Ah[r*QAHLD + c]     = a;
            *(__half2*)&Ah[r*QAHLD + c + 2] = b;
        }
    }
    __syncthreads();

    auto issueB = [&](int st, int tt){
        int k0 = (tt & 3) << 5;
        int n0 = nbase + (tt >> 2)*128;
        #pragma unroll
        for (int i=0;i<2;i++){
            int idx = tid + i*256;
            int r = idx >> 4, c8 = (idx & 15)*8;
            cp16(&Bh[st][r*QBHLD + c8], &Bw[(size_t)(k0+r)*QKVLD + n0 + c8]);
        }
        asm volatile("cp.async.commit_group;\n");
    };

    issueB(0, 0);
    for (int c = 0; c < NCHUNK; c++){
        wmma::fragment<wmma::accumulator,16,16,16,float> acc[2][4];
        #pragma unroll
        for (int i=0;i<2;i++)
            #pragma unroll
            for (int j=0;j<4;j++) wmma::fill_fragment(acc[i][j], 0.0f);

        for (int kt = 0; kt < 4; kt++){
            int tt = c*4 + kt;
            if (tt+1 < NCHUNK*4){
                issueB((tt+1)&1, tt+1);
                asm volatile("cp.async.wait_group 1;\n" ::: "memory");
            } else {
                asm volatile("cp.async.wait_group 0;\n" ::: "memory");
            }
            __syncthreads();
            int st = tt & 1;
            #pragma unroll
            for (int ks = 0; ks < 32; ks += 16){
                wmma::fragment<wmma::matrix_a,16,16,16,__half,wmma::row_major> af[2];
                #pragma unroll
                for (int i=0;i<2;i++)
                    wmma::load_matrix_sync(af[i], &Ah[(wm*32 + i*16)*QAHLD + kt*32 + ks], QAHLD);
                #pragma unroll
                for (int j=0;j<4;j++){
                    wmma::fragment<wmma::matrix_b,16,16,16,__half,wmma::row_major> bf;
                    wmma::load_matrix_sync(bf, &Bh[st][ks*QBHLD + wn*64 + j*16], QBHLD);
                    wmma::mma_sync(acc[0][j], af[0], bf, acc[0][j]);
                    wmma::mma_sync(acc[1][j], af[1], bf, acc[1][j]);
                }
            }
            __syncthreads();
        }

        int n0 = nbase + c*128;
        #pragma unroll
        for (int pass = 0; pass < 2; pass++){
            if (wn == pass){
                #pragma unroll
                for (int i=0;i<2;i++)
                    #pragma unroll
                    for (int j=0;j<4;j++)
                        wmma::store_matrix_sync(&Cs[(wm*32 + i*16)*QCSLD + j*16],
                                                acc[i][j], QCSLD, wmma::mem_row_major);
            }
            __syncthreads();
            #pragma unroll
            for (int i=0;i<4;i++){
                int idx = tid + i*256;
                int r = idx >> 3, c8 = (idx & 7)*8;
                float4 v0 = *(float4*)&Cs[r*QCSLD + c8];
                float4 v1 = *(float4*)&Cs[r*QCSLD + c8 + 4];
                __half2 hh[4];
                hh[0] = __float22half2_rn(make_float2(v0.x, v0.y));
                hh[1] = __float22half2_rn(make_float2(v0.z, v0.w));
                hh[2] = __float22half2_rn(make_float2(v1.x, v1.y));
                hh[3] = __float22half2_rn(make_float2(v1.z, v1.w));
                *(uint4*)&C[(size_t)(m0+r)*QKVLD + n0 + pass*64 + c8] = *(uint4*)hh;
            }
            __syncthreads();
        }
    }
}

/* ---------------- out-proj GEMM v4: dual-A (o + o2), 3-stage ring ----------------
   h = (o1 + o2) @ Wout + bias + resid. BM=64, BN=128, BK=32, 8 warps (2M x 4N). */
#define OAHLD 40
#define OBHLD 136
#define OA_ST (64*OAHLD)
#define OB_ST (32*OBHLD)
#define OST_B ((2*OA_ST + OB_ST)*2)    /* 18944 B per stage */
#define OCSLD 136
#define WOUT_SMEM (3*OST_B)            /* 56832 B >= 64*OCSLD*4 = 34816 */

__global__ void __launch_bounds__(256)
wgemm_out(const __half* __restrict__ A1, const __half* __restrict__ A2,
          const __half* __restrict__ B, float* __restrict__ C,
          const float* __restrict__ bias, const float* __restrict__ resid)
{
    extern __shared__ char smp[];
    int m0 = blockIdx.x * 64;
    int tid = threadIdx.x, w = tid >> 5;
    int wm = w & 1, wn = w >> 1;

    wmma::fragment<wmma::accumulator,16,16,16,float> acc[2][2];
    #pragma unroll
    for (int i=0;i<2;i++)
        #pragma unroll
        for (int j=0;j<2;j++) wmma::fill_fragment(acc[i][j], 0.0f);

    auto issue = [&](int t){
        char* stg = smp + (t % 3)*OST_B;
        __half* As1 = (__half*)stg;
        __half* As2 = (__half*)stg + OA_ST;
        __half* Bst = (__half*)stg + 2*OA_ST;
        int k0 = t << 5;
        {
            int r = tid >> 2, c8 = (tid & 3)*8;
            cp16(&As1[r*OAHLD + c8], &A1[(size_t)(m0+r)*INNER + k0 + c8]);
            cp16(&As2[r*OAHLD + c8], &A2[(size_t)(m0+r)*INNER + k0 + c8]);
        }
        #pragma unroll
        for (int i=0;i<2;i++){
            int idx = tid + i*256;
            int r = idx >> 4, c8 = (idx & 15)*8;
            cp16(&Bst[r*OBHLD + c8], &B[(size_t)(k0+r)*DD + c8]);
        }
        asm volatile("cp.async.commit_group;\n");
    };

    const int nt = INNER >> 5;
    issue(0);
    issue(1);
    for (int t = 0; t < nt; t++){
        if (t < nt-1) { asm volatile("cp.async.wait_group 1;\n" ::: "memory"); }
        else          { asm volatile("cp.async.wait_group 0;\n" ::: "memory"); }
        __syncthreads();
        if (t+2 < nt) issue(t+2);
        char* stg = smp + (t % 3)*OST_B;
        __half* As1 = (__half*)stg;
        __half* As2 = (__half*)stg + OA_ST;
        __half* Bst = (__half*)stg + 2*OA_ST;
        #pragma unroll
        for (int ks = 0; ks < 32; ks += 16){
            wmma::fragment<wmma::matrix_a,16,16,16,__half,wmma::row_major> af[2], ag;
            wmma::fragment<wmma::matrix_b,16,16,16,__half,wmma::row_major> bf[2];
            #pragma unroll
            for (int i=0;i<2;i++){
                wmma::load_matrix_sync(af[i], &As1[(wm*32 + i*16)*OAHLD + ks], OAHLD);
                wmma::load_matrix_sync(ag,    &As2[(wm*32 + i*16)*OAHLD + ks], OAHLD);
                #pragma unroll
                for (int e=0; e<af[i].num_elements; e++)
                    af[i].x[e] = __hadd(af[i].x[e], ag.x[e]);
            }
            #pragma unroll
            for (int j=0;j<2;j++)
                wmma::load_matrix_sync(bf[j], &Bst[ks*OBHLD + wn*32 + j*16], OBHLD);
            #pragma unroll
            for (int i=0;i<2;i++)
                #pragma unroll
                for (int j=0;j<2;j++)
                    wmma::mma_sync(acc[i][j], af[i], bf[j], acc[i][j]);
        }
    }
    __syncthreads();

    float* Cs = (float*)smp;
    #pragma unroll
    for (int i=0;i<2;i++)
        #pragma unroll
        for (int j=0;j<2;j++)
            wmma::store_matrix_sync(&Cs[(wm*32 + i*16)*OCSLD + wn*32 + j*16],
                                    acc[i][j], OCSLD, wmma::mem_row_major);
    __syncthreads();

    #pragma unroll
    for (int i=0;i<8;i++){
        int idx = tid + i*256;
        int r = idx >> 5, c4 = (idx & 31)*4;
        float4 v  = *(float4*)&Cs[r*OCSLD + c4];
        float4 bb = *(const float4*)&bias[c4];
        float4 rr = *(const float4*)&resid[(size_t)(m0+r)*DD + c4];
        v.x += bb.x + rr.x; v.y += bb.y + rr.y;
        v.z += bb.z + rr.z; v.w += bb.w + rr.w;
        *(float4*)&C[(size_t)(m0+r)*DD + c4] = v;
    }
}

/* ---------------- variable attention v3 (unchanged) ---------------- */
#define VLD2 136
#define VWB  (48*VLD2)
#define VATTN_SMEM (HH*VWB*2)          /* 104448 B */

__global__ void __launch_bounds__(256, 2)
vattn_kernel(const __half* __restrict__ qkv, __half* __restrict__ o)
{
    extern __shared__ __half vs[];
    int bw = blockIdx.x;
    int w  = threadIdx.x >> 5, lane = threadIdx.x & 31;
    int lg = lane >> 2, lq = lane & 3;
    __half* Wb = vs + w*VWB;
    const __half* base = qkv + (size_t)bw*FF*QKVLD + w*DD;
    __half* op = o + (size_t)bw*FF*INNER + w*DD;

    #pragma unroll
    for (int i=0;i<24;i++){
        int idx = lane + i*32;
        int r = idx >> 4, c8 = (idx & 15)*8;
        int f = r & 15, sel = r >> 4;
        cp16(&Wb[r*VLD2 + c8], base + (size_t)f*QKVLD + sel*INNER + c8);
    }
    asm volatile("cp.async.commit_group;\n");
    asm volatile("cp.async.wait_group 0;\n" ::: "memory");
    __syncwarp();

    wmma::fragment<wmma::accumulator,16,16,16,float> sf;
    wmma::fill_fragment(sf, 0.0f);
    #pragma unroll
    for (int ks = 0; ks < DD; ks += 16){
        wmma::fragment<wmma::matrix_a,16,16,16,__half,wmma::row_major> af;
        wmma::fragment<wmma::matrix_b,16,16,16,__half,wmma::col_major> bf;
        wmma::load_matrix_sync(af, Wb + ks, VLD2);
        wmma::load_matrix_sync(bf, Wb + 16*VLD2 + ks, VLD2);
        wmma::mma_sync(sf, af, bf, sf);
    }

    float m2[2], s2[2], rinv[2];
    #pragma unroll
    for (int hh=0; hh<2; hh++){
        int e0 = hh*2;
        float m = fmaxf(fmaxf(sf.x[e0], sf.x[e0+1]), fmaxf(sf.x[e0+4], sf.x[e0+5]));
        m = fmaxf(m, __shfl_xor_sync(~0u, m, 1));
        m = fmaxf(m, __shfl_xor_sync(~0u, m, 2));
        m2[hh] = m;
    }
    #pragma unroll
    for (int hh=0; hh<2; hh++) s2[hh] = 0.f;
    #pragma unroll
    for (int e=0; e<8; e++){
        int hh = (e>>1)&1;
        float p = fexp((sf.x[e] - m2[hh])*SCALE);
        sf.x[e] = p;
        s2[hh] += p;
    }
    #pragma unroll
    for (int hh=0; hh<2; hh++){
        float s = s2[hh];
        s += __shfl_xor_sync(~0u, s, 1);
        s += __shfl_xor_sync(~0u, s, 2);
        rinv[hh] = 1.0f/s;
    }

    __syncwarp();
    #pragma unroll
    for (int e=0; e<8; e+=2){
        int hh = (e>>1)&1;
        int row = lg + 8*hh;
        int col = lq*2 + 8*(e>>2);
        *(__half2*)&Wb[row*VLD2 + col] =
            __float22half2_rn(make_float2(sf.x[e], sf.x[e+1]));
    }
    __syncwarp();

    wmma::fragment<wmma::matrix_a,16,16,16,__half,wmma::row_major> pf;
    wmma::load_matrix_sync(pf, Wb, VLD2);

    #pragma unroll
    for (int n0 = 0; n0 < DD; n0 += 16){
        wmma::fragment<wmma::accumulator,16,16,16,float> of;
        wmma::fill_fragment(of, 0.0f);
        wmma::fragment<wmma::matrix_b,16,16,16,__half,wmma::row_major> vf;
        wmma::load_matrix_sync(vf, Wb + 32*VLD2 + n0, VLD2);
        wmma::mma_sync(of, pf, vf, of);
        #pragma unroll
        for (int e=0; e<8; e+=2){
            int hh = (e>>1)&1;
            int row = lg + 8*hh;
            int col = n0 + lq*2 + 8*(e>>2);
            float inv = rinv[hh];
            *(__half2*)&op[(size_t)row*INNER + col] =
                __float22half2_rn(make_float2(of.x[e]*inv, of.x[e+1]*inv));
        }
    }
}

/* ---------------- fused temporal attention (R10 TI=64), plain-store epilogue ---------------- */
#define TI    64
#define KHLD  136
#define PHLD  264
#define OFF_PH (256*KHLD*2)                    /* 69632  */
#define OFF_RR (OFF_PH + TI*PHLD*2)            /* 103424 */
#define TATTN_SMEM (OFF_RR + TI*4*4)           /* 104448 */

__global__ void __launch_bounds__(256, 2)
tattn_kernel(const __half* __restrict__ qkv, __half* __restrict__ o2)
{
    extern __shared__ char smb[];
    __half* Kh = (__half*)smb;
    __half* Ph = (__half*)(smb + OFF_PH);
    float*  RR = (float*) (smb + OFF_RR);

    int batch = blockIdx.y;
    int hd = batch & 7, f = (batch >> 3) & 15, b = batch >> 7;
    int i0 = blockIdx.x * TI;
    size_t baseQ = ((size_t)(b*WW)*FF + f)*QKVLD + hd*DD;
    size_t baseK = baseQ + INNER;
    size_t baseV = baseQ + 2*INNER;
    size_t baseO = ((size_t)(b*WW)*FF + f)*INNER + hd*DD;
    int tid = threadIdx.x, w = tid >> 5, lane = tid & 31;
    int wm = w & 1, wn = w >> 1;
    int lg = lane >> 2, lq = lane & 3;

    #pragma unroll
    for (int i=0;i<16;i++){
        int idx = tid + i*256;
        int r = idx >> 4, c8 = (idx & 15)*8;
        cp16(&Kh[r*KHLD + c8], &qkv[baseK + (size_t)r*RS + c8]);
    }
    asm volatile("cp.async.commit_group;\n");
    asm volatile("cp.async.wait_group 0;\n" ::: "memory");
    __syncthreads();

    const __half* qp = qkv + baseQ + (size_t)i0*RS;
    wmma::fragment<wmma::accumulator,16,16,16,float> sf[2][4];
    #pragma unroll
    for (int i=0;i<2;i++)
        #pragma unroll
        for (int j=0;j<4;j++) wmma::fill_fragment(sf[i][j], 0.0f);
    #pragma unroll
    for (int ks=0; ks<DD; ks+=16){
        wmma::fragment<wmma::matrix_a,16,16,16,__half,wmma::row_major> af[2];
        wmma::fragment<wmma::matrix_b,16,16,16,__half,wmma::col_major> bf[4];
        #pragma unroll
        for (int i=0;i<2;i++)
            wmma::load_matrix_sync(af[i], qp + (size_t)(wm*32 + i*16)*RS + ks, RS);
        #pragma unroll
        for (int j=0;j<4;j++)
            wmma::load_matrix_sync(bf[j], &Kh[(wn*64 + j*16)*KHLD + ks], KHLD);
        #pragma unroll
        for (int i=0;i<2;i++)
            #pragma unroll
            for (int j=0;j<4;j++)
                wmma::mma_sync(sf[i][j], af[i], bf[j], sf[i][j]);
    }
    __syncthreads();

    #pragma unroll
    for (int i=0;i<16;i++){
        int idx = tid + i*256;
        int r = idx >> 4, c8 = (idx & 15)*8;
        cp16(&Kh[r*KHLD + c8], &qkv[baseV + (size_t)r*RS + c8]);
    }
    asm volatile("cp.async.commit_group;\n");

    float pm[4];
    #pragma unroll
    for (int i=0;i<2;i++)
        #pragma unroll
        for (int hh=0;hh<2;hh++){
            float m = -1e30f;
            #pragma unroll
            for (int j=0;j<4;j++){
                float* x = sf[i][j].x;
                int e0 = hh*2;
                m = fmaxf(m, fmaxf(fmaxf(x[e0], x[e0+1]), fmaxf(x[e0+4], x[e0+5])));
            }
            pm[i*2+hh] = m;
        }
    #pragma unroll
    for (int u=0;u<4;u++){
        pm[u] = fmaxf(pm[u], __shfl_xor_sync(~0u, pm[u], 1));
        pm[u] = fmaxf(pm[u], __shfl_xor_sync(~0u, pm[u], 2));
    }
    if (lq == 0){
        #pragma unroll
        for (int i=0;i<2;i++)
            #pragma unroll
            for (int hh=0;hh<2;hh++)
                RR[(wm*32 + i*16 + hh*8 + lg)*4 + wn] = pm[i*2+hh];
    }
    __syncthreads();
    float gmax[4];
    #pragma unroll
    for (int i=0;i<2;i++)
        #pragma unroll
        for (int hh=0;hh<2;hh++){
            const float* rr = &RR[(wm*32 + i*16 + hh*8 + lg)*4];
            gmax[i*2+hh] = fmaxf(fmaxf(rr[0], rr[1]), fmaxf(rr[2], rr[3]));
        }
    __syncthreads();

    float ps[4] = {0.f, 0.f, 0.f, 0.f};
    #pragma unroll
    for (int i=0;i<2;i++)
        #pragma unroll
        for (int j=0;j<4;j++){
            float* x = sf[i][j].x;
            #pragma unroll
            for (int e=0;e<8;e++){
                int hh = (e>>1)&1;
                float p = fexp((x[e] - gmax[i*2+hh])*SCALE);
                x[e] = p;
                ps[i*2+hh] += p;
            }
        }
    #pragma unroll
    for (int u=0;u<4;u++){
        ps[u] += __shfl_xor_sync(~0u, ps[u], 1);
        ps[u] += __shfl_xor_sync(~0u, ps[u], 2);
    }
    if (lq == 0){
        #pragma unroll
        for (int i=0;i<2;i++)
            #pragma unroll
            for (int hh=0;hh<2;hh++)
                RR[(wm*32 + i*16 + hh*8 + lg)*4 + wn] = ps[i*2+hh];
    }
    __syncthreads();
    float rinv[4];
    #pragma unroll
    for (int i=0;i<2;i++)
        #pragma unroll
        for (int hh=0;hh<2;hh++){
            const float* rr = &RR[(wm*32 + i*16 + hh*8 + lg)*4];
            rinv[i*2+hh] = 1.0f/(rr[0]+rr[1]+rr[2]+rr[3]);
        }

    #pragma unroll
    for (int i=0;i<2;i++)
        #pragma unroll
        for (int j=0;j<4;j++){
            float* x = sf[i][j].x;
            #pragma unroll
            for (int e=0;e<8;e+=2){
                int hh = (e>>1)&1;
                int row = wm*32 + i*16 + hh*8 + lg;
                int col = wn*64 + j*16 + lq*2 + 8*(e>>2);
                *(__half2*)&Ph[row*PHLD + col] =
                    __float22half2_rn(make_float2(x[e], x[e+1]));
            }
        }
    asm volatile("cp.async.wait_group 0;\n" ::: "memory");
    __syncthreads();

    wmma::fragment<wmma::accumulator,16,16,16,float> of[2][2];
    #pragma unroll
    for (int i=0;i<2;i++)
        #pragma unroll
        for (int j=0;j<2;j++) wmma::fill_fragment(of[i][j], 0.0f);
    #pragma unroll
    for (int ks=0; ks<WW; ks+=16){
        wmma::fragment<wmma::matrix_a,16,16,16,__half,wmma::row_major> pf[2];
        wmma::fragment<wmma::matrix_b,16,16,16,__half,wmma::row_major> vf[2];
        #pragma unroll
        for (int i=0;i<2;i++)
            wmma::load_matrix_sync(pf[i], &Ph[(wm*32 + i*16)*PHLD + ks], PHLD);
        #pragma unroll
        for (int j=0;j<2;j++)
            wmma::load_matrix_sync(vf[j], &Kh[ks*KHLD + wn*32 + j*16], KHLD);
        #pragma unroll
        for (int i=0;i<2;i++)
            #pragma unroll
            for (int j=0;j<2;j++)
                wmma::mma_sync(of[i][j], pf[i], vf[j], of[i][j]);
    }

    /* epilogue: plain store o2 = of * rinv (no RMW) */
    #pragma unroll
    for (int i=0;i<2;i++)
        #pragma unroll
        for (int j=0;j<2;j++){
            float* x = of[i][j].x;
            #pragma unroll
            for (int e=0;e<8;e+=2){
                int hh = (e>>1)&1;
                int row = wm*32 + i*16 + hh*8 + lg;
                int col = wn*32 + j*16 + lq*2 + 8*(e>>2);
                float inv = rinv[i*2+hh];
                *(__half2*)&o2[baseO + (size_t)(i0+row)*RO + col] =
                    __float22half2_rn(make_float2(x[e]*inv, x[e+1]*inv));
            }
        }
}

/* ---------------- head ---------------- */
__global__ void head_kernel(const float* __restrict__ wh, const float* __restrict__ bh,
                            float* __restrict__ out)
{
    int bw = blockIdx.x;
    int n = threadIdx.x >> 5, lane = threadIdx.x & 31;
    const float* hrow = g_h + (size_t)bw*(FF*DD);
    float acc = 0.f;
    #pragma unroll 4
    for (int k = lane; k < FF*DD; k += 32)
        acc += hrow[k]*wh[k*FF + n];
    #pragma unroll
    for (int o=16;o>0;o>>=1) acc += __shfl_xor_sync(~0u, acc, o);
    if (lane == 0) out[bw*FF + n] = acc + bh[n];
}

/* ---------------- launcher: vattn || tattn via two streams ---------------- */
extern "C" void kernel_launch(void* const* d_in, const int* in_sizes, int n_in,
                              void* d_out, int out_size)
{
    (void)in_sizes; (void)n_in; (void)out_size;
    const float* x   = (const float*)d_in[0];
    const float* w1  = (const float*)d_in[1];
    const float* b1  = (const float*)d_in[2];
    const float* w2  = (const float*)d_in[3];
    const float* b2  = (const float*)d_in[4];
    const float* w3  = (const float*)d_in[5];
    const float* b3  = (const float*)d_in[6];
    const float* wv  = (const float*)d_in[7];
    const float* bv  = (const float*)d_in[8];
    const float* lng = (const float*)d_in[9];
    const float* lnb = (const float*)d_in[10];
    const float* wq  = (const float*)d_in[11];
    const float* wo  = (const float*)d_in[12];
    const float* bo  = (const float*)d_in[13];
    const float* wh  = (const float*)d_in[14];
    const float* bh  = (const float*)d_in[15];
    float* out = (float*)d_out;

    float *p_h; __half *p_qkv, *p_o, *p_o2, *p_wqh, *p_woh;
    cudaGetSymbolAddress((void**)&p_h,   g_h);
    cudaGetSymbolAddress((void**)&p_qkv, g_qkv);
    cudaGetSymbolAddress((void**)&p_o,   g_o);
    cudaGetSymbolAddress((void**)&p_o2,  g_o2);
    cudaGetSymbolAddress((void**)&p_wqh, g_wqh);
    cudaGetSymbolAddress((void**)&p_woh, g_woh);

    static cudaStream_t s2 = nullptr;
    static cudaEvent_t evA[NL], evB[NL];
    if (!s2){
        cudaStreamCreateWithFlags(&s2, cudaStreamNonBlocking);
        for (int l = 0; l < NL; l++){
            cudaEventCreateWithFlags(&evA[l], cudaEventDisableTiming);
            cudaEventCreateWithFlags(&evB[l], cudaEventDisableTiming);
        }
    }

    cudaFuncSetAttribute(tattn_kernel,
        cudaFuncAttributeMaxDynamicSharedMemorySize, TATTN_SMEM);
    cudaFuncSetAttribute(vattn_kernel,
        cudaFuncAttributeMaxDynamicSharedMemorySize, VATTN_SMEM);
    cudaFuncSetAttribute(qkvln_kernel,
        cudaFuncAttributeMaxDynamicSharedMemorySize, QKV_SMEM);
    cudaFuncSetAttribute(wgemm_out,
        cudaFuncAttributeMaxDynamicSharedMemorySize, WOUT_SMEM);

    cvtw_kernel<<<(NQW + 255)/256, 256>>>(wq, wo);
    embed_kernel<<<NT, DD>>>(x, w1, b1, w2, b2, w3, b3, wv, bv);

    for (int l = 0; l < NL; l++) {
        /* fused LN + qkv GEMM : [32768,128]@[128,3072] */
        qkvln_kernel<<<dim3(2, NT/128), 256, QKV_SMEM>>>(
            p_h, p_wqh + (size_t)l*DD*QKVLD, p_qkv, lng + l*DD, lnb + l*DD);

        /* fork: tattn on s2 (writes g_o2), vattn on default (writes g_o) */
        cudaEventRecord(evA[l], 0);
        cudaStreamWaitEvent(s2, evA[l], 0);
        tattn_kernel<<<dim3(WW/TI, BB*FF*HH), 256, TATTN_SMEM, s2>>>(p_qkv, p_o2);
        cudaEventRecord(evB[l], s2);

        vattn_kernel<<<BB*WW, 256, VATTN_SMEM>>>(p_qkv, p_o);

        /* join, then h = (o + o2) @ Wout[l] + b_out[l] + h */
        cudaStreamWaitEvent(0, evB[l], 0);
        wgemm_out<<<NT/64, 256, WOUT_SMEM>>>(
            p_o, p_o2, p_woh + (size_t)l*INNER*DD, p_h, bo + l*DD, p_h);
    }

    head_kernel<<<BB*WW, 512>>>(wh, bh, out);
}

// round 16
// speedup vs baseline: 1.1460x; 1.0776x over previous
#include <cuda_runtime.h>
#include <cuda_fp16.h>
#include <mma.h>
#include <math.h>
using namespace nvcuda;

#define BB 8
#define WW 256
#define FF 16
#define DD 128
#define HH 8
#define NL 4
#define INNER 1024
#define NT (BB*WW*FF)          /* 32768 tokens */
#define QKVLD 3072
#define SCALE 0.08838834764831845f   /* 128^-0.5 */
#define RS (FF*QKVLD)          /* 49152: row stride (per w) in qkv */
#define RO (FF*INNER)          /* 16384: row stride (per w) in o   */

/* ---------------- scratch (static __device__, no allocation) ---------------- */
__device__ float  g_h  [NT*DD];
__device__ __half g_qkv[(size_t)NT*QKVLD];
__device__ __half g_o  [(size_t)NT*INNER];          /* vattn output   */
__device__ __half g_o2 [(size_t)NT*INNER];          /* tattn output   */
__device__ __half g_wqh[NL*DD*QKVLD];
__device__ __half g_woh[NL*INNER*DD];

/* ---------------- fast exp on the FMA pipe ---------------- */
__device__ __forceinline__ float fexp(float x)
{
    x = fmaxf(x, -80.0f);
    float z  = x * 1.4426950408889634f;
    float zj = z + 12582912.0f;
    int   k  = __float_as_int(zj) - 0x4B400000;
    float f  = z - (zj - 12582912.0f);
    float p  = 1.3333558146e-3f;
    p = p*f + 9.6181291076e-3f;
    p = p*f + 5.5504108665e-2f;
    p = p*f + 2.4022650696e-1f;
    p = p*f + 6.9314718056e-1f;
    p = p*f + 1.0f;
    return __int_as_float(__float_as_int(p) + (k << 23));
}

__device__ __forceinline__ void cp16(void* smem_dst, const void* gmem_src)
{
    unsigned d = (unsigned)__cvta_generic_to_shared(smem_dst);
    asm volatile("cp.async.cg.shared.global [%0], [%1], 16;\n" :: "r"(d), "l"(gmem_src));
}

/* ---------------- weight conversion fp32 -> fp16 (once per launch) ---------------- */
#define NQW (NL*DD*QKVLD)
#define NOW (NL*INNER*DD)
__global__ void cvtw_kernel(const float* __restrict__ wq, const float* __restrict__ wo)
{
    int i = blockIdx.x*256 + threadIdx.x;
    if (i < NQW) g_wqh[i] = __float2half(wq[i]);
    if (i < NOW) g_woh[i] = __float2half(wo[i]);
}

/* ---------------- embed: convs + value proj + positional encoding ---------------- */
__global__ void embed_kernel(const float* __restrict__ x,
    const float* __restrict__ w1, const float* __restrict__ b1,
    const float* __restrict__ w2, const float* __restrict__ b2,
    const float* __restrict__ w3, const float* __restrict__ b3,
    const float* __restrict__ wv, const float* __restrict__ bv)
{
    int tok = blockIdx.x;
    int d   = threadIdx.x;
    int f   = tok % FF;
    int bw  = tok / FF;
    int w   = bw % WW;
    const float* xp = x + (size_t)(bw - w)*FF + f;

    float s0 = xp[(size_t)w*FF];
    float c1 = b1[f];
    #pragma unroll
    for (int j = 0; j < 4; j++) { int wi = w - (3-j);    if (wi >= 0) c1 += xp[(size_t)wi*FF]*w1[f*4+j]; }
    float c2 = b2[f];
    #pragma unroll
    for (int j = 0; j < 8; j++) { int wi = w - (7-j)*2;  if (wi >= 0) c2 += xp[(size_t)wi*FF]*w2[f*8+j]; }
    float c3 = b3[f];
    #pragma unroll
    for (int j = 0; j < 16; j++){ int wi = w - (15-j)*3; if (wi >= 0) c3 += xp[(size_t)wi*FF]*w3[f*16+j]; }

    float e = s0*wv[d] + c1*wv[DD+d] + c2*wv[2*DD+d] + c3*wv[3*DD+d] + bv[d];

    int   i2  = (d >> 1) * 2;
    float div = expf(-logf(10000.0f)/(float)DD * (float)i2);
    float ang = (float)w * div;
    float pe  = (d & 1) ? cosf(ang) : sinf(ang);

    g_h[(size_t)tok*DD + d] = e + pe;
}

/* ---------------- fused LN + QKV GEMM (R10 2-stage version) ---------------- */
#define QAHLD 136
#define QBHLD 136
#define QB_ST (32*QBHLD)
#define QCSLD 72
#define NCHUNK 12
#define QKV_SMEM (128*QAHLD*2 + 2*QB_ST*2 + 128*QCSLD*4)   /* 89088 B */

__global__ void __launch_bounds__(256)
qkvln_kernel(const float* __restrict__ h, const __half* __restrict__ Bw,
             __half* __restrict__ C,
             const float* __restrict__ gam, const float* __restrict__ bet)
{
    extern __shared__ char smp[];
    __half* Ah    = (__half*)smp;
    __half* Bh[2] = { (__half*)(smp + 128*QAHLD*2),
                      (__half*)(smp + 128*QAHLD*2) + QB_ST };
    float*  Cs    = (float*)(smp + 128*QAHLD*2 + 2*QB_ST*2);

    int m0 = blockIdx.y * 128;
    int nbase = blockIdx.x * (NCHUNK*128);
    int tid = threadIdx.x, w = tid >> 5;
    int wm = w & 3, wn = w >> 2;

    if (tid < 128) Cs[tid] = gam[tid];
    else           Cs[tid] = bet[tid-128];
    __syncthreads();

    {
        int r = tid >> 1, c0 = (tid & 1)*64;
        const float* hr = h + (size_t)(m0+r)*DD + c0;
        float s = 0.f, ss = 0.f;
        #pragma unroll
        for (int i=0;i<16;i++){
            float4 v = *(const float4*)&hr[i*4];
            s  += v.x+v.y+v.z+v.w;
            ss += v.x*v.x+v.y*v.y+v.z*v.z+v.w*v.w;
        }
        s  += __shfl_xor_sync(~0u, s, 1);
        ss += __shfl_xor_sync(~0u, ss, 1);
        float mean = s * (1.0f/DD);
        float rstd = rsqrtf(ss*(1.0f/DD) - mean*mean + 1e-5f);
        #pragma unroll
        for (int i=0;i<16;i++){
            float4 v = *(const float4*)&hr[i*4];
            int c = c0 + i*4;
            __half2 a = __float22half2_rn(make_float2(
                (v.x-mean)*rstd*Cs[c+0] + Cs[128+c+0],
                (v.y-mean)*rstd*Cs[c+1] + Cs[128+c+1]));
            __half2 b = __float22half2_rn(make_float2(
                (v.z-mean)*rstd*Cs[c+2] + Cs[128+c+2],
                (v.w-mean)*rstd*Cs[c+3] + Cs[128+c+3]));
            *(__half2*)&Ah[r*QAHLD + c]     = a;
            *(__half2*)&Ah[r*QAHLD + c + 2] = b;
        }
    }
    __syncthreads();

    auto issueB = [&](int st, int tt){
        int k0 = (tt & 3) << 5;
        int n0 = nbase + (tt >> 2)*128;
        #pragma unroll
        for (int i=0;i<2;i++){
            int idx = tid + i*256;
            int r = idx >> 4, c8 = (idx & 15)*8;
            cp16(&Bh[st][r*QBHLD + c8], &Bw[(size_t)(k0+r)*QKVLD + n0 + c8]);
        }
        asm volatile("cp.async.commit_group;\n");
    };

    issueB(0, 0);
    for (int c = 0; c < NCHUNK; c++){
        wmma::fragment<wmma::accumulator,16,16,16,float> acc[2][4];
        #pragma unroll
        for (int i=0;i<2;i++)
            #pragma unroll
            for (int j=0;j<4;j++) wmma::fill_fragment(acc[i][j], 0.0f);

        for (int kt = 0; kt < 4; kt++){
            int tt = c*4 + kt;
            if (tt+1 < NCHUNK*4){
                issueB((tt+1)&1, tt+1);
                asm volatile("cp.async.wait_group 1;\n" ::: "memory");
            } else {
                asm volatile("cp.async.wait_group 0;\n" ::: "memory");
            }
            __syncthreads();
            int st = tt & 1;
            #pragma unroll
            for (int ks = 0; ks < 32; ks += 16){
                wmma::fragment<wmma::matrix_a,16,16,16,__half,wmma::row_major> af[2];
                #pragma unroll
                for (int i=0;i<2;i++)
                    wmma::load_matrix_sync(af[i], &Ah[(wm*32 + i*16)*QAHLD + kt*32 + ks], QAHLD);
                #pragma unroll
                for (int j=0;j<4;j++){
                    wmma::fragment<wmma::matrix_b,16,16,16,__half,wmma::row_major> bf;
                    wmma::load_matrix_sync(bf, &Bh[st][ks*QBHLD + wn*64 + j*16], QBHLD);
                    wmma::mma_sync(acc[0][j], af[0], bf, acc[0][j]);
                    wmma::mma_sync(acc[1][j], af[1], bf, acc[1][j]);
                }
            }
            __syncthreads();
        }

        int n0 = nbase + c*128;
        #pragma unroll
        for (int pass = 0; pass < 2; pass++){
            if (wn == pass){
                #pragma unroll
                for (int i=0;i<2;i++)
                    #pragma unroll
                    for (int j=0;j<4;j++)
                        wmma::store_matrix_sync(&Cs[(wm*32 + i*16)*QCSLD + j*16],
                                                acc[i][j], QCSLD, wmma::mem_row_major);
            }
            __syncthreads();
            #pragma unroll
            for (int i=0;i<4;i++){
                int idx = tid + i*256;
                int r = idx >> 3, c8 = (idx & 7)*8;
                float4 v0 = *(float4*)&Cs[r*QCSLD + c8];
                float4 v1 = *(float4*)&Cs[r*QCSLD + c8 + 4];
                __half2 hh[4];
                hh[0] = __float22half2_rn(make_float2(v0.x, v0.y));
                hh[1] = __float22half2_rn(make_float2(v0.z, v0.w));
                hh[2] = __float22half2_rn(make_float2(v1.x, v1.y));
                hh[3] = __float22half2_rn(make_float2(v1.z, v1.w));
                *(uint4*)&C[(size_t)(m0+r)*QKVLD + n0 + pass*64 + c8] = *(uint4*)hh;
            }
            __syncthreads();
        }
    }
}

/* ---------------- out-proj GEMM v4: dual-A (o + o2), 3-stage ring ---------------- */
#define OAHLD 40
#define OBHLD 136
#define OA_ST (64*OAHLD)
#define OB_ST (32*OBHLD)
#define OST_B ((2*OA_ST + OB_ST)*2)    /* 18944 B per stage */
#define OCSLD 136
#define WOUT_SMEM (3*OST_B)            /* 56832 B */

__global__ void __launch_bounds__(256)
wgemm_out(const __half* __restrict__ A1, const __half* __restrict__ A2,
          const __half* __restrict__ B, float* __restrict__ C,
          const float* __restrict__ bias, const float* __restrict__ resid)
{
    extern __shared__ char smp[];
    int m0 = blockIdx.x * 64;
    int tid = threadIdx.x, w = tid >> 5;
    int wm = w & 1, wn = w >> 1;

    wmma::fragment<wmma::accumulator,16,16,16,float> acc[2][2];
    #pragma unroll
    for (int i=0;i<2;i++)
        #pragma unroll
        for (int j=0;j<2;j++) wmma::fill_fragment(acc[i][j], 0.0f);

    auto issue = [&](int t){
        char* stg = smp + (t % 3)*OST_B;
        __half* As1 = (__half*)stg;
        __half* As2 = (__half*)stg + OA_ST;
        __half* Bst = (__half*)stg + 2*OA_ST;
        int k0 = t << 5;
        {
            int r = tid >> 2, c8 = (tid & 3)*8;
            cp16(&As1[r*OAHLD + c8], &A1[(size_t)(m0+r)*INNER + k0 + c8]);
            cp16(&As2[r*OAHLD + c8], &A2[(size_t)(m0+r)*INNER + k0 + c8]);
        }
        #pragma unroll
        for (int i=0;i<2;i++){
            int idx = tid + i*256;
            int r = idx >> 4, c8 = (idx & 15)*8;
            cp16(&Bst[r*OBHLD + c8], &B[(size_t)(k0+r)*DD + c8]);
        }
        asm volatile("cp.async.commit_group;\n");
    };

    const int nt = INNER >> 5;
    issue(0);
    issue(1);
    for (int t = 0; t < nt; t++){
        if (t < nt-1) { asm volatile("cp.async.wait_group 1;\n" ::: "memory"); }
        else          { asm volatile("cp.async.wait_group 0;\n" ::: "memory"); }
        __syncthreads();
        if (t+2 < nt) issue(t+2);
        char* stg = smp + (t % 3)*OST_B;
        __half* As1 = (__half*)stg;
        __half* As2 = (__half*)stg + OA_ST;
        __half* Bst = (__half*)stg + 2*OA_ST;
        #pragma unroll
        for (int ks = 0; ks < 32; ks += 16){
            wmma::fragment<wmma::matrix_a,16,16,16,__half,wmma::row_major> af[2], ag;
            wmma::fragment<wmma::matrix_b,16,16,16,__half,wmma::row_major> bf[2];
            #pragma unroll
            for (int i=0;i<2;i++){
                wmma::load_matrix_sync(af[i], &As1[(wm*32 + i*16)*OAHLD + ks], OAHLD);
                wmma::load_matrix_sync(ag,    &As2[(wm*32 + i*16)*OAHLD + ks], OAHLD);
                #pragma unroll
                for (int e=0; e<af[i].num_elements; e++)
                    af[i].x[e] = __hadd(af[i].x[e], ag.x[e]);
            }
            #pragma unroll
            for (int j=0;j<2;j++)
                wmma::load_matrix_sync(bf[j], &Bst[ks*OBHLD + wn*32 + j*16], OBHLD);
            #pragma unroll
            for (int i=0;i<2;i++)
                #pragma unroll
                for (int j=0;j<2;j++)
                    wmma::mma_sync(acc[i][j], af[i], bf[j], acc[i][j]);
        }
    }
    __syncthreads();

    float* Cs = (float*)smp;
    #pragma unroll
    for (int i=0;i<2;i++)
        #pragma unroll
        for (int j=0;j<2;j++)
            wmma::store_matrix_sync(&Cs[(wm*32 + i*16)*OCSLD + wn*32 + j*16],
                                    acc[i][j], OCSLD, wmma::mem_row_major);
    __syncthreads();

    #pragma unroll
    for (int i=0;i<8;i++){
        int idx = tid + i*256;
        int r = idx >> 5, c4 = (idx & 31)*4;
        float4 v  = *(float4*)&Cs[r*OCSLD + c4];
        float4 bb = *(const float4*)&bias[c4];
        float4 rr = *(const float4*)&resid[(size_t)(m0+r)*DD + c4];
        v.x += bb.x + rr.x; v.y += bb.y + rr.y;
        v.z += bb.z + rr.z; v.w += bb.w + rr.w;
        *(float4*)&C[(size_t)(m0+r)*DD + c4] = v;
    }
}

/* ---------------- variable attention v3 (unchanged) ---------------- */
#define VLD2 136
#define VWB  (48*VLD2)
#define VATTN_SMEM (HH*VWB*2)          /* 104448 B */

__global__ void __launch_bounds__(256, 2)
vattn_kernel(const __half* __restrict__ qkv, __half* __restrict__ o)
{
    extern __shared__ __half vs[];
    int bw = blockIdx.x;
    int w  = threadIdx.x >> 5, lane = threadIdx.x & 31;
    int lg = lane >> 2, lq = lane & 3;
    __half* Wb = vs + w*VWB;
    const __half* base = qkv + (size_t)bw*FF*QKVLD + w*DD;
    __half* op = o + (size_t)bw*FF*INNER + w*DD;

    #pragma unroll
    for (int i=0;i<24;i++){
        int idx = lane + i*32;
        int r = idx >> 4, c8 = (idx & 15)*8;
        int f = r & 15, sel = r >> 4;
        cp16(&Wb[r*VLD2 + c8], base + (size_t)f*QKVLD + sel*INNER + c8);
    }
    asm volatile("cp.async.commit_group;\n");
    asm volatile("cp.async.wait_group 0;\n" ::: "memory");
    __syncwarp();

    wmma::fragment<wmma::accumulator,16,16,16,float> sf;
    wmma::fill_fragment(sf, 0.0f);
    #pragma unroll
    for (int ks = 0; ks < DD; ks += 16){
        wmma::fragment<wmma::matrix_a,16,16,16,__half,wmma::row_major> af;
        wmma::fragment<wmma::matrix_b,16,16,16,__half,wmma::col_major> bf;
        wmma::load_matrix_sync(af, Wb + ks, VLD2);
        wmma::load_matrix_sync(bf, Wb + 16*VLD2 + ks, VLD2);
        wmma::mma_sync(sf, af, bf, sf);
    }

    float m2[2], s2[2], rinv[2];
    #pragma unroll
    for (int hh=0; hh<2; hh++){
        int e0 = hh*2;
        float m = fmaxf(fmaxf(sf.x[e0], sf.x[e0+1]), fmaxf(sf.x[e0+4], sf.x[e0+5]));
        m = fmaxf(m, __shfl_xor_sync(~0u, m, 1));
        m = fmaxf(m, __shfl_xor_sync(~0u, m, 2));
        m2[hh] = m;
    }
    #pragma unroll
    for (int hh=0; hh<2; hh++) s2[hh] = 0.f;
    #pragma unroll
    for (int e=0; e<8; e++){
        int hh = (e>>1)&1;
        float p = fexp((sf.x[e] - m2[hh])*SCALE);
        sf.x[e] = p;
        s2[hh] += p;
    }
    #pragma unroll
    for (int hh=0; hh<2; hh++){
        float s = s2[hh];
        s += __shfl_xor_sync(~0u, s, 1);
        s += __shfl_xor_sync(~0u, s, 2);
        rinv[hh] = 1.0f/s;
    }

    __syncwarp();
    #pragma unroll
    for (int e=0; e<8; e+=2){
        int hh = (e>>1)&1;
        int row = lg + 8*hh;
        int col = lq*2 + 8*(e>>2);
        *(__half2*)&Wb[row*VLD2 + col] =
            __float22half2_rn(make_float2(sf.x[e], sf.x[e+1]));
    }
    __syncwarp();

    wmma::fragment<wmma::matrix_a,16,16,16,__half,wmma::row_major> pf;
    wmma::load_matrix_sync(pf, Wb, VLD2);

    #pragma unroll
    for (int n0 = 0; n0 < DD; n0 += 16){
        wmma::fragment<wmma::accumulator,16,16,16,float> of;
        wmma::fill_fragment(of, 0.0f);
        wmma::fragment<wmma::matrix_b,16,16,16,__half,wmma::row_major> vf;
        wmma::load_matrix_sync(vf, Wb + 32*VLD2 + n0, VLD2);
        wmma::mma_sync(of, pf, vf, of);
        #pragma unroll
        for (int e=0; e<8; e+=2){
            int hh = (e>>1)&1;
            int row = lg + 8*hh;
            int col = n0 + lq*2 + 8*(e>>2);
            float inv = rinv[hh];
            *(__half2*)&op[(size_t)row*INNER + col] =
                __float22half2_rn(make_float2(of.x[e]*inv, of.x[e+1]*inv));
        }
    }
}

/* ---------------- fused temporal attention v4: Q staged in smem (aliases Ph) ----------------
   TI=64, 256 threads, 2 blocks/SM. Q (64x128) cp.async'd with K; phase-1 A-fragments
   from smem. Q region is dead after phase 1; Ph overwrites it. smem unchanged 104448 B. */
#define TI    64
#define KHLD  136
#define QHLD  136
#define PHLD  264
#define OFF_PH (256*KHLD*2)                    /* 69632: Q first, then Ph */
#define OFF_RR (OFF_PH + TI*PHLD*2)            /* 103424 */
#define TATTN_SMEM (OFF_RR + TI*4*4)           /* 104448 */

__global__ void __launch_bounds__(256, 2)
tattn_kernel(const __half* __restrict__ qkv, __half* __restrict__ o2)
{
    extern __shared__ char smb[];
    __half* Kh = (__half*)smb;                 /* K, then V */
    __half* Qs = (__half*)(smb + OFF_PH);      /* Q; Ph overwrites after phase 1 */
    __half* Ph = (__half*)(smb + OFF_PH);
    float*  RR = (float*) (smb + OFF_RR);

    int batch = blockIdx.y;
    int hd = batch & 7, f = (batch >> 3) & 15, b = batch >> 7;
    int i0 = blockIdx.x * TI;
    size_t baseQ = ((size_t)(b*WW)*FF + f)*QKVLD + hd*DD;
    size_t baseK = baseQ + INNER;
    size_t baseV = baseQ + 2*INNER;
    size_t baseO = ((size_t)(b*WW)*FF + f)*INNER + hd*DD;
    int tid = threadIdx.x, w = tid >> 5, lane = tid & 31;
    int wm = w & 1, wn = w >> 1;
    int lg = lane >> 2, lq = lane & 3;

    /* async load K (256x128) + Q (64x128) in one group */
    #pragma unroll
    for (int i=0;i<16;i++){
        int idx = tid + i*256;
        int r = idx >> 4, c8 = (idx & 15)*8;
        cp16(&Kh[r*KHLD + c8], &qkv[baseK + (size_t)r*RS + c8]);
    }
    #pragma unroll
    for (int i=0;i<4;i++){
        int idx = tid + i*256;
        int r = idx >> 4, c8 = (idx & 15)*8;
        cp16(&Qs[r*QHLD + c8], &qkv[baseQ + (size_t)(i0+r)*RS + c8]);
    }
    asm volatile("cp.async.commit_group;\n");
    asm volatile("cp.async.wait_group 0;\n" ::: "memory");
    __syncthreads();

    /* phase 1: S = Q @ K^T (64 x 256), all operands in smem */
    wmma::fragment<wmma::accumulator,16,16,16,float> sf[2][4];
    #pragma unroll
    for (int i=0;i<2;i++)
        #pragma unroll
        for (int j=0;j<4;j++) wmma::fill_fragment(sf[i][j], 0.0f);
    #pragma unroll
    for (int ks=0; ks<DD; ks+=16){
        wmma::fragment<wmma::matrix_a,16,16,16,__half,wmma::row_major> af[2];
        wmma::fragment<wmma::matrix_b,16,16,16,__half,wmma::col_major> bf[4];
        #pragma unroll
        for (int i=0;i<2;i++)
            wmma::load_matrix_sync(af[i], &Qs[(wm*32 + i*16)*QHLD + ks], QHLD);
        #pragma unroll
        for (int j=0;j<4;j++)
            wmma::load_matrix_sync(bf[j], &Kh[(wn*64 + j*16)*KHLD + ks], KHLD);
        #pragma unroll
        for (int i=0;i<2;i++)
            #pragma unroll
            for (int j=0;j<4;j++)
                wmma::mma_sync(sf[i][j], af[i], bf[j], sf[i][j]);
    }
    __syncthreads();                       /* all warps done reading K and Q */

    /* issue V load into Kh (overlaps register softmax) */
    #pragma unroll
    for (int i=0;i<16;i++){
        int idx = tid + i*256;
        int r = idx >> 4, c8 = (idx & 15)*8;
        cp16(&Kh[r*KHLD + c8], &qkv[baseV + (size_t)r*RS + c8]);
    }
    asm volatile("cp.async.commit_group;\n");

    /* register softmax */
    float pm[4];
    #pragma unroll
    for (int i=0;i<2;i++)
        #pragma unroll
        for (int hh=0;hh<2;hh++){
            float m = -1e30f;
            #pragma unroll
            for (int j=0;j<4;j++){
                float* x = sf[i][j].x;
                int e0 = hh*2;
                m = fmaxf(m, fmaxf(fmaxf(x[e0], x[e0+1]), fmaxf(x[e0+4], x[e0+5])));
            }
            pm[i*2+hh] = m;
        }
    #pragma unroll
    for (int u=0;u<4;u++){
        pm[u] = fmaxf(pm[u], __shfl_xor_sync(~0u, pm[u], 1));
        pm[u] = fmaxf(pm[u], __shfl_xor_sync(~0u, pm[u], 2));
    }
    if (lq == 0){
        #pragma unroll
        for (int i=0;i<2;i++)
            #pragma unroll
            for (int hh=0;hh<2;hh++)
                RR[(wm*32 + i*16 + hh*8 + lg)*4 + wn] = pm[i*2+hh];
    }
    __syncthreads();
    float gmax[4];
    #pragma unroll
    for (int i=0;i<2;i++)
        #pragma unroll
        for (int hh=0;hh<2;hh++){
            const float* rr = &RR[(wm*32 + i*16 + hh*8 + lg)*4];
            gmax[i*2+hh] = fmaxf(fmaxf(rr[0], rr[1]), fmaxf(rr[2], rr[3]));
        }
    __syncthreads();

    float ps[4] = {0.f, 0.f, 0.f, 0.f};
    #pragma unroll
    for (int i=0;i<2;i++)
        #pragma unroll
        for (int j=0;j<4;j++){
            float* x = sf[i][j].x;
            #pragma unroll
            for (int e=0;e<8;e++){
                int hh = (e>>1)&1;
                float p = fexp((x[e] - gmax[i*2+hh])*SCALE);
                x[e] = p;
                ps[i*2+hh] += p;
            }
        }
    #pragma unroll
    for (int u=0;u<4;u++){
        ps[u] += __shfl_xor_sync(~0u, ps[u], 1);
        ps[u] += __shfl_xor_sync(~0u, ps[u], 2);
    }
    if (lq == 0){
        #pragma unroll
        for (int i=0;i<2;i++)
            #pragma unroll
            for (int hh=0;hh<2;hh++)
                RR[(wm*32 + i*16 + hh*8 + lg)*4 + wn] = ps[i*2+hh];
    }
    __syncthreads();
    float rinv[4];
    #pragma unroll
    for (int i=0;i<2;i++)
        #pragma unroll
        for (int hh=0;hh<2;hh++){
            const float* rr = &RR[(wm*32 + i*16 + hh*8 + lg)*4];
            rinv[i*2+hh] = 1.0f/(rr[0]+rr[1]+rr[2]+rr[3]);
        }

    /* write unnormalized probs (half) to Ph (overwrites dead Q region) */
    #pragma unroll
    for (int i=0;i<2;i++)
        #pragma unroll
        for (int j=0;j<4;j++){
            float* x = sf[i][j].x;
            #pragma unroll
            for (int e=0;e<8;e+=2){
                int hh = (e>>1)&1;
                int row = wm*32 + i*16 + hh*8 + lg;
                int col = wn*64 + j*16 + lq*2 + 8*(e>>2);
                *(__half2*)&Ph[row*PHLD + col] =
                    __float22half2_rn(make_float2(x[e], x[e+1]));
            }
        }
    asm volatile("cp.async.wait_group 0;\n" ::: "memory");
    __syncthreads();

    /* phase 2: O = P @ V (64 x 128, K=256). warp tile 32x32. */
    wmma::fragment<wmma::accumulator,16,16,16,float> of[2][2];
    #pragma unroll
    for (int i=0;i<2;i++)
        #pragma unroll
        for (int j=0;j<2;j++) wmma::fill_fragment(of[i][j], 0.0f);
    #pragma unroll
    for (int ks=0; ks<WW; ks+=16){
        wmma::fragment<wmma::matrix_a,16,16,16,__half,wmma::row_major> pf[2];
        wmma::fragment<wmma::matrix_b,16,16,16,__half,wmma::row_major> vf[2];
        #pragma unroll
        for (int i=0;i<2;i++)
            wmma::load_matrix_sync(pf[i], &Ph[(wm*32 + i*16)*PHLD + ks], PHLD);
        #pragma unroll
        for (int j=0;j<2;j++)
            wmma::load_matrix_sync(vf[j], &Kh[ks*KHLD + wn*32 + j*16], KHLD);
        #pragma unroll
        for (int i=0;i<2;i++)
            #pragma unroll
            for (int j=0;j<2;j++)
                wmma::mma_sync(of[i][j], pf[i], vf[j], of[i][j]);
    }

    /* epilogue: plain store o2 = of * rinv */
    #pragma unroll
    for (int i=0;i<2;i++)
        #pragma unroll
        for (int j=0;j<2;j++){
            float* x = of[i][j].x;
            #pragma unroll
            for (int e=0;e<8;e+=2){
                int hh = (e>>1)&1;
                int row = wm*32 + i*16 + hh*8 + lg;
                int col = wn*32 + j*16 + lq*2 + 8*(e>>2);
                float inv = rinv[i*2+hh];
                *(__half2*)&o2[baseO + (size_t)(i0+row)*RO + col] =
                    __float22half2_rn(make_float2(x[e]*inv, x[e+1]*inv));
            }
        }
}

/* ---------------- head ---------------- */
__global__ void head_kernel(const float* __restrict__ wh, const float* __restrict__ bh,
                            float* __restrict__ out)
{
    int bw = blockIdx.x;
    int n = threadIdx.x >> 5, lane = threadIdx.x & 31;
    const float* hrow = g_h + (size_t)bw*(FF*DD);
    float acc = 0.f;
    #pragma unroll 4
    for (int k = lane; k < FF*DD; k += 32)
        acc += hrow[k]*wh[k*FF + n];
    #pragma unroll
    for (int o=16;o>0;o>>=1) acc += __shfl_xor_sync(~0u, acc, o);
    if (lane == 0) out[bw*FF + n] = acc + bh[n];
}

/* ---------------- launcher: vattn || tattn via two streams ---------------- */
extern "C" void kernel_launch(void* const* d_in, const int* in_sizes, int n_in,
                              void* d_out, int out_size)
{
    (void)in_sizes; (void)n_in; (void)out_size;
    const float* x   = (const float*)d_in[0];
    const float* w1  = (const float*)d_in[1];
    const float* b1  = (const float*)d_in[2];
    const float* w2  = (const float*)d_in[3];
    const float* b2  = (const float*)d_in[4];
    const float* w3  = (const float*)d_in[5];
    const float* b3  = (const float*)d_in[6];
    const float* wv  = (const float*)d_in[7];
    const float* bv  = (const float*)d_in[8];
    const float* lng = (const float*)d_in[9];
    const float* lnb = (const float*)d_in[10];
    const float* wq  = (const float*)d_in[11];
    const float* wo  = (const float*)d_in[12];
    const float* bo  = (const float*)d_in[13];
    const float* wh  = (const float*)d_in[14];
    const float* bh  = (const float*)d_in[15];
    float* out = (float*)d_out;

    float *p_h; __half *p_qkv, *p_o, *p_o2, *p_wqh, *p_woh;
    cudaGetSymbolAddress((void**)&p_h,   g_h);
    cudaGetSymbolAddress((void**)&p_qkv, g_qkv);
    cudaGetSymbolAddress((void**)&p_o,   g_o);
    cudaGetSymbolAddress((void**)&p_o2,  g_o2);
    cudaGetSymbolAddress((void**)&p_wqh, g_wqh);
    cudaGetSymbolAddress((void**)&p_woh, g_woh);

    static cudaStream_t s2 = nullptr;
    static cudaEvent_t evA[NL], evB[NL];
    if (!s2){
        cudaStreamCreateWithFlags(&s2, cudaStreamNonBlocking);
        for (int l = 0; l < NL; l++){
            cudaEventCreateWithFlags(&evA[l], cudaEventDisableTiming);
            cudaEventCreateWithFlags(&evB[l], cudaEventDisableTiming);
        }
    }

    cudaFuncSetAttribute(tattn_kernel,
        cudaFuncAttributeMaxDynamicSharedMemorySize, TATTN_SMEM);
    cudaFuncSetAttribute(vattn_kernel,
        cudaFuncAttributeMaxDynamicSharedMemorySize, VATTN_SMEM);
    cudaFuncSetAttribute(qkvln_kernel,
        cudaFuncAttributeMaxDynamicSharedMemorySize, QKV_SMEM);
    cudaFuncSetAttribute(wgemm_out,
        cudaFuncAttributeMaxDynamicSharedMemorySize, WOUT_SMEM);

    cvtw_kernel<<<(NQW + 255)/256, 256>>>(wq, wo);
    embed_kernel<<<NT, DD>>>(x, w1, b1, w2, b2, w3, b3, wv, bv);

    for (int l = 0; l < NL; l++) {
        /* fused LN + qkv GEMM : [32768,128]@[128,3072] */
        qkvln_kernel<<<dim3(2, NT/128), 256, QKV_SMEM>>>(
            p_h, p_wqh + (size_t)l*DD*QKVLD, p_qkv, lng + l*DD, lnb + l*DD);

        /* fork: tattn on s2 (writes g_o2), vattn on default (writes g_o) */
        cudaEventRecord(evA[l], 0);
        cudaStreamWaitEvent(s2, evA[l], 0);
        tattn_kernel<<<dim3(WW/TI, BB*FF*HH), 256, TATTN_SMEM, s2>>>(p_qkv, p_o2);
        cudaEventRecord(evB[l], s2);

        vattn_kernel<<<BB*WW, 256, VATTN_SMEM>>>(p_qkv, p_o);

        /* join, then h = (o + o2) @ Wout[l] + b_out[l] + h */
        cudaStreamWaitEvent(0, evB[l], 0);
        wgemm_out<<<NT/64, 256, WOUT_SMEM>>>(
            p_o, p_o2, p_woh + (size_t)l*INNER*DD, p_h, bo + l*DD, p_h);
    }

    head_kernel<<<BB*WW, 512>>>(wh, bh, out);
}